// round 9
// baseline (speedup 1.0000x reference)
#include <cuda_runtime.h>
#include <cuda_bf16.h>
#include <stdint.h>
#include <math.h>

// ---------------- problem constants ----------------
#define BB   2
#define SS   2048
#define DIN  2048
#define NH   16
#define KVH  4
#define HD   128
#define GRP  (NH / KVH)            // 4
#define DOUT (NH * HD)             // 2048
#define DKV  (KVH * HD)            // 512
#define BS   (BB * SS)             // 4096
#define NQKV (DOUT + 2 * DKV)      // 3072

// ---------------- dense gemm tiling ----------------
#define BM 128
#define BN 128
#define BK 32
#define BKP 40
#define NTHR 256

#define OFF_AHI 0
#define OFF_ALO (BM * BKP * 2)
#define OFF_BHI (2 * BM * BKP * 2)
#define OFF_BLO (3 * BM * BKP * 2)
#define STAGE   (4 * BM * BKP * 2)      // 40960 B
#define SMEM_DYN3 (3 * STAGE)           // 122880 B

// ---------------- fused attention tiling ----------------
#define FBM 128
#define FBN 64
#define KSP 136
#define VSP 72
#define QSP 136
#define KTILE (64 * KSP * 2)
#define VTILE (128 * VSP * 2)
#define FSTAGE (2 * KTILE + 2 * VTILE)   // 71680 B
#define FSMEM (2 * FSTAGE)               // 143360 B
#define QBYTES (128 * QSP * 2)

typedef __nv_bfloat16 bf;

// ---------------- device scratch ----------------
__device__ float g_vp [(size_t)BS * DKV];

__device__ bf g_xh [(size_t)BS * DIN],  g_xl [(size_t)BS * DIN];
__device__ bf g_WTh[(size_t)NQKV * DIN], g_WTl[(size_t)NQKV * DIN]; // q|k|v rows
__device__ bf g_WoTh[(size_t)DIN * DOUT], g_WoTl[(size_t)DIN * DOUT];
__device__ bf g_qhmh[(size_t)BS * DOUT],  g_qhml[(size_t)BS * DOUT];
__device__ bf g_khmh[(size_t)BS * DKV],   g_khml[(size_t)BS * DKV];
__device__ bf g_vTh [(size_t)BB * KVH * HD * SS], g_vTl[(size_t)BB * KVH * HD * SS];
__device__ bf g_ctxh[(size_t)BS * DOUT],  g_ctxl[(size_t)BS * DOUT];

// ---------------- helpers ----------------
__device__ __forceinline__ uint32_t smem_u32(const void* p) {
    uint32_t a;
    asm("{ .reg .u64 t; cvta.to.shared.u64 t, %1; cvt.u32.u64 %0, t; }"
        : "=r"(a) : "l"(p));
    return a;
}
__device__ __forceinline__ uint32_t pack_bf(bf a, bf b) {
    uint16_t ua = *reinterpret_cast<uint16_t*>(&a);
    uint16_t ub = *reinterpret_cast<uint16_t*>(&b);
    return (uint32_t)ua | ((uint32_t)ub << 16);
}
__device__ __forceinline__ void split2(float x, float y, bf* hi, bf* lo,
                                       size_t idx) {
    bf h0 = __float2bfloat16(x), h1 = __float2bfloat16(y);
    bf l0 = __float2bfloat16(x - __bfloat162float(h0));
    bf l1 = __float2bfloat16(y - __bfloat162float(h1));
    *reinterpret_cast<uint32_t*>(hi + idx) = pack_bf(h0, h1);
    *reinterpret_cast<uint32_t*>(lo + idx) = pack_bf(l0, l1);
}
__device__ __forceinline__ void cpasync16(uint32_t dst, const void* src) {
    asm volatile("cp.async.cg.shared.global [%0], [%1], 16;"
                 :: "r"(dst), "l"(src));
}
__device__ __forceinline__ void ldm4(uint32_t* d, uint32_t addr) {
    asm volatile("ldmatrix.sync.aligned.m8n8.x4.shared.b16 {%0,%1,%2,%3}, [%4];"
                 : "=r"(d[0]), "=r"(d[1]), "=r"(d[2]), "=r"(d[3]) : "r"(addr));
}
__device__ __forceinline__ void mma16816(float* c, const uint32_t* a, const uint32_t* b) {
    asm volatile(
        "mma.sync.aligned.m16n8k16.row.col.f32.bf16.bf16.f32 "
        "{%0,%1,%2,%3}, {%4,%5,%6,%7}, {%8,%9}, {%0,%1,%2,%3};"
        : "+f"(c[0]), "+f"(c[1]), "+f"(c[2]), "+f"(c[3])
        : "r"(a[0]), "r"(a[1]), "r"(a[2]), "r"(a[3]), "r"(b[0]), "r"(b[1]));
}

// ---------------- 3-stage pipelined HMMA bf16x3 NT compute ----------------
// acc = A[m0:+128, 0:kmax] @ B[n0:+128, 0:kmax]^T   (per-thread fragments)
__device__ __forceinline__ void mma_compute(
    char* dyn,
    const bf* __restrict__ Ahi, const bf* __restrict__ Alo, int lda,
    const bf* __restrict__ Bhi, const bf* __restrict__ Blo, int ldb,
    int kmax, int m0, int n0, float acc[4][4][4])
{
    const int tid  = threadIdx.x;
    const int lane = tid & 31;
    const int wid  = tid >> 5;
    const int wm   = wid & 1;
    const int wn   = wid >> 1;
    const uint32_t sb = smem_u32(dyn);

#pragma unroll
    for (int i = 0; i < 4; i++)
#pragma unroll
        for (int j = 0; j < 4; j++)
#pragma unroll
            for (int k = 0; k < 4; k++) acc[i][j][k] = 0.f;

    const uint32_t aoff =
        (uint32_t)(((wm * 64 + (lane & 15)) * BKP + ((lane >> 4) * 8)) * 2);
    const uint32_t boff =
        (uint32_t)(((wn * 32 + ((lane >> 4) * 8) + (lane & 7)) * BKP +
                    (((lane >> 3) & 1) * 8)) * 2);

    const int frow = tid >> 2;
    const int fkg  = (tid & 3) * 8;
    const int nch = kmax / BK;

    auto fill = [&](int ch) {
        if (ch < nch) {
            const uint32_t st = sb + (uint32_t)(ch % 3) * STAGE;
            const int k0 = ch * BK;
#pragma unroll
            for (int i = 0; i < 2; i++) {
                const int row = frow + i * 64;
                const uint32_t so = (uint32_t)(row * BKP + fkg) * 2;
                const size_t ai = (size_t)(m0 + row) * lda + k0 + fkg;
                const size_t bi = (size_t)(n0 + row) * ldb + k0 + fkg;
                cpasync16(st + OFF_AHI + so, Ahi + ai);
                cpasync16(st + OFF_ALO + so, Alo + ai);
                cpasync16(st + OFF_BHI + so, Bhi + bi);
                cpasync16(st + OFF_BLO + so, Blo + bi);
            }
        }
        asm volatile("cp.async.commit_group;");
    };

    fill(0);
    fill(1);

    for (int ch = 0; ch < nch; ch++) {
        fill(ch + 2);
        asm volatile("cp.async.wait_group 2;");
        __syncthreads();

        const uint32_t base = sb + (uint32_t)(ch % 3) * STAGE;
        const uint32_t aHi = base + OFF_AHI + aoff;
        const uint32_t aLo = base + OFF_ALO + aoff;
        const uint32_t bHi = base + OFF_BHI + boff;
        const uint32_t bLo = base + OFF_BLO + boff;
#pragma unroll
        for (int ks = 0; ks < 2; ks++) {
            uint32_t bh[8], bl[8];
            ldm4(bh + 0, bHi + ks * 32);
            ldm4(bh + 4, bHi + 16 * BKP * 2 + ks * 32);
            ldm4(bl + 0, bLo + ks * 32);
            ldm4(bl + 4, bLo + 16 * BKP * 2 + ks * 32);
#pragma unroll
            for (int mt = 0; mt < 4; mt++) {
                uint32_t ah[4], al[4];
                ldm4(ah, aHi + mt * 16 * BKP * 2 + ks * 32);
                ldm4(al, aLo + mt * 16 * BKP * 2 + ks * 32);
#pragma unroll
                for (int nt = 0; nt < 4; nt++) {
                    mma16816(acc[mt][nt], ah, &bh[nt * 2]);
                    mma16816(acc[mt][nt], al, &bh[nt * 2]);
                    mma16816(acc[mt][nt], ah, &bl[nt * 2]);
                }
            }
        }
        __syncthreads();
    }
}

// ---------------- O-projection GEMM (plain fp32 epilogue) ----------------
__global__ void __launch_bounds__(NTHR)
k_mma_dense(const bf* __restrict__ Ahi, const bf* __restrict__ Alo, int lda,
            const bf* __restrict__ Bhi, const bf* __restrict__ Blo, int ldb,
            float* __restrict__ C, int ldc, int K)
{
    extern __shared__ char dyn[];
    const int m0 = blockIdx.y * BM, n0 = blockIdx.x * BN;
    float acc[4][4][4];
    mma_compute(dyn, Ahi, Alo, lda, Bhi, Blo, ldb, K, m0, n0, acc);

    const int lane = threadIdx.x & 31, wid = threadIdx.x >> 5;
    const int wm = wid & 1, wn = wid >> 1;
#pragma unroll
    for (int mt = 0; mt < 4; mt++)
#pragma unroll
        for (int half = 0; half < 2; half++) {
            const int row = m0 + wm * 64 + mt * 16 + (lane >> 2) + half * 8;
#pragma unroll
            for (int nt = 0; nt < 4; nt++) {
                const int col = n0 + wn * 32 + nt * 8 + (lane & 3) * 2;
                *reinterpret_cast<float2*>(C + (size_t)row * ldc + col) =
                    make_float2(acc[mt][nt][half * 2 + 0],
                                acc[mt][nt][half * 2 + 1]);
            }
        }
}

// ---------------- merged QKV GEMM + fused rmsnorm/rope/split epilogue ----
__global__ void __launch_bounds__(NTHR)
k_mma_qkv(const bf* __restrict__ xh, const bf* __restrict__ xl,
          const bf* __restrict__ Wh, const bf* __restrict__ Wl,
          float* __restrict__ vp,
          bf* __restrict__ qhmh, bf* __restrict__ qhml,
          bf* __restrict__ khmh, bf* __restrict__ khml,
          const float* __restrict__ cosb, const float* __restrict__ sinb,
          const float* __restrict__ qs, const float* __restrict__ ks)
{
    extern __shared__ char dyn[];
    const int m0 = blockIdx.y * BM, n0 = blockIdx.x * BN;
    float acc[4][4][4];
    mma_compute(dyn, xh, xl, DIN, Wh, Wl, DIN, DIN, m0, n0, acc);

    const int lane = threadIdx.x & 31, wid = threadIdx.x >> 5;
    const int wm = wid & 1, wn = wid >> 1;

    if (n0 >= DOUT + DKV) {
        // ---- V tile: plain fp32 store (vtrans consumes) ----
        const int coff = n0 - DOUT - DKV;
#pragma unroll
        for (int mt = 0; mt < 4; mt++)
#pragma unroll
            for (int half = 0; half < 2; half++) {
                const int row = m0 + wm * 64 + mt * 16 + (lane >> 2) + half * 8;
#pragma unroll
                for (int nt = 0; nt < 4; nt++) {
                    const int col = coff + wn * 32 + nt * 8 + (lane & 3) * 2;
                    *reinterpret_cast<float2*>(vp + (size_t)row * DKV + col) =
                        make_float2(acc[mt][nt][half * 2 + 0],
                                    acc[mt][nt][half * 2 + 1]);
                }
            }
        return;
    }

    // ---- Q/K tile: rmsnorm + rope + split, head-major output ----
    const bool isQ = (n0 < DOUT);
    const float* scale = isQ ? qs : ks;
    bf* oh = isQ ? qhmh : khmh;
    bf* ol = isQ ? qhml : khml;
    const int nheads = isQ ? NH : KVH;
    const int h = (isQ ? n0 : (n0 - DOUT)) / HD;
    const float alpha = isQ ? 0.08838834764831845f : 1.0f;

    float* rsum = reinterpret_cast<float*>(dyn);                 // [128][4]
    float* stg  = reinterpret_cast<float*>(dyn + 2048);          // [128][132]

    // 1) partial sum of squares per row (32 cols per warp)
#pragma unroll
    for (int mt = 0; mt < 4; mt++)
#pragma unroll
        for (int half = 0; half < 2; half++) {
            const int rl = wm * 64 + mt * 16 + (lane >> 2) + half * 8;
            float part = 0.f;
#pragma unroll
            for (int nt = 0; nt < 4; nt++) {
                const float vx = acc[mt][nt][half * 2 + 0];
                const float vy = acc[mt][nt][half * 2 + 1];
                part += vx * vx + vy * vy;
            }
            part += __shfl_xor_sync(0xffffffffu, part, 1);
            part += __shfl_xor_sync(0xffffffffu, part, 2);
            if ((lane & 3) == 0) rsum[rl * 4 + wn] = part;
        }
    __syncthreads();

    // 2) normalize + scale into smem staging tile
#pragma unroll
    for (int mt = 0; mt < 4; mt++)
#pragma unroll
        for (int half = 0; half < 2; half++) {
            const int rl = wm * 64 + mt * 16 + (lane >> 2) + half * 8;
            const float tot = rsum[rl * 4 + 0] + rsum[rl * 4 + 1] +
                              rsum[rl * 4 + 2] + rsum[rl * 4 + 3];
            const float rinv = rsqrtf(tot * (1.0f / HD) + 1e-6f) * alpha;
#pragma unroll
            for (int nt = 0; nt < 4; nt++) {
                const int c = wn * 32 + nt * 8 + (lane & 3) * 2;
                stg[rl * 132 + c]     = acc[mt][nt][half * 2 + 0] * rinv * scale[c];
                stg[rl * 132 + c + 1] = acc[mt][nt][half * 2 + 1] * rinv * scale[c + 1];
            }
        }
    __syncthreads();

    // 3) rope + split-store head-major
#pragma unroll
    for (int mt = 0; mt < 4; mt++)
#pragma unroll
        for (int half = 0; half < 2; half++) {
            const int rl = wm * 64 + mt * 16 + (lane >> 2) + half * 8;
            const int row = m0 + rl;
            const int b = row >> 11, pos = row & (SS - 1);
#pragma unroll
            for (int nt = 0; nt < 4; nt++) {
                const int c = wn * 32 + nt * 8 + (lane & 3) * 2;
                const float xn0 = stg[rl * 132 + c];
                const float xn1 = stg[rl * 132 + c + 1];
                const int p = (c + 64) & 127;
                const float s0 = stg[rl * 132 + p];
                const float s1 = stg[rl * 132 + p + 1];
                const float rot0 = (c < 64) ? -s0 : s0;
                const float rot1 = (c < 64) ? -s1 : s1;
                const float o0 = xn0 * cosb[pos * HD + c]     + rot0 * sinb[pos * HD + c];
                const float o1 = xn1 * cosb[pos * HD + c + 1] + rot1 * sinb[pos * HD + c + 1];
                const size_t oi = ((size_t)(b * nheads + h) * SS + pos) * HD + c;
                split2(o0, o1, oh, ol, oi);
            }
        }
}

// ---------------- fused flash attention (bf16x3 HMMA) ----------------
__global__ void __launch_bounds__(256, 1)
k_attn(const bf* __restrict__ qhp, const bf* __restrict__ qlp,
       const bf* __restrict__ khp, const bf* __restrict__ klp,
       const bf* __restrict__ vhp, const bf* __restrict__ vlp,
       bf* __restrict__ ctxh, bf* __restrict__ ctxl)
{
    extern __shared__ char dyn[];
    const uint32_t sb = smem_u32(dyn);
    const int tid = threadIdx.x, lane = tid & 31, w = tid >> 5;
    const int bh = blockIdx.y, b = bh / NH, h = bh % NH;
    const int kvh = (bh % NH) / GRP;
    const int m0 = ((int)gridDim.x - 1 - (int)blockIdx.x) * FBM;
    const size_t qo = (size_t)bh * SS * HD;
    const size_t ko = (size_t)(b * KVH + kvh) * SS * HD;
    const size_t vo = (size_t)(b * KVH + kvh) * HD * SS;

#pragma unroll
    for (int it = 0; it < 8; it++) {
        const int c = tid + it * 256;
        const int row = c >> 4, col = (c & 15) * 8;
        const size_t gi = qo + (size_t)(m0 + row) * HD + col;
        cpasync16(sb + (uint32_t)(row * QSP + col) * 2, qhp + gi);
        cpasync16(sb + QBYTES + (uint32_t)(row * QSP + col) * 2, qlp + gi);
    }
    asm volatile("cp.async.commit_group;");
    asm volatile("cp.async.wait_group 0;");
    __syncthreads();

    uint32_t qfh[8][4], qfl[8][4];
    {
        const uint32_t ab = sb +
            (uint32_t)(((w * 16 + (lane & 15)) * QSP + (lane >> 4) * 8) * 2);
#pragma unroll
        for (int kk = 0; kk < 8; kk++) {
            ldm4(qfh[kk], ab + kk * 32);
            ldm4(qfl[kk], ab + QBYTES + kk * 32);
        }
    }
    __syncthreads();

    const int nb = m0 / FBN + 2;

    auto load_kv = [&](int i) {
        if (i < nb) {
            const int n0 = i * FBN;
            const uint32_t bufb = sb + (uint32_t)(i & 1) * FSTAGE;
#pragma unroll
            for (int it = 0; it < 4; it++) {
                const int c = tid + it * 256;
                const int krow = c >> 4, kcol = (c & 15) * 8;
                const size_t gk = ko + (size_t)(n0 + krow) * HD + kcol;
                cpasync16(bufb + (uint32_t)(krow * KSP + kcol) * 2, khp + gk);
                cpasync16(bufb + KTILE + (uint32_t)(krow * KSP + kcol) * 2, klp + gk);
                const int vrow = c >> 3, vcol = (c & 7) * 8;
                const size_t gv = vo + (size_t)vrow * SS + n0 + vcol;
                cpasync16(bufb + 2 * KTILE + (uint32_t)(vrow * VSP + vcol) * 2, vhp + gv);
                cpasync16(bufb + 2 * KTILE + VTILE + (uint32_t)(vrow * VSP + vcol) * 2, vlp + gv);
            }
        }
        asm volatile("cp.async.commit_group;");
    };

    load_kv(0);
    load_kv(1);

    float ctxa[16][4];
#pragma unroll
    for (int j = 0; j < 16; j++)
#pragma unroll
        for (int e = 0; e < 4; e++) ctxa[j][e] = 0.f;
    float mrow0 = -1e30f, mrow8 = -1e30f, lrow0 = 0.f, lrow8 = 0.f;

    const uint32_t kboff =
        (uint32_t)((((lane >> 4) * 8 + (lane & 7)) * KSP + ((lane >> 3) & 1) * 8) * 2);
    const uint32_t vboff =
        (uint32_t)((((lane >> 4) * 8 + (lane & 7)) * VSP + ((lane >> 3) & 1) * 8) * 2);
    const int r0g = m0 + w * 16 + (lane >> 2);
    const int cquad = 2 * (lane & 3);

    for (int i = 0; i < nb; i++) {
        asm volatile("cp.async.wait_group 1;");
        __syncthreads();
        const uint32_t base = sb + (uint32_t)(i & 1) * FSTAGE;
        const int n0 = i * FBN;

        float s[8][4];
#pragma unroll
        for (int j = 0; j < 8; j++)
#pragma unroll
            for (int e = 0; e < 4; e++) s[j][e] = 0.f;

        const uint32_t kb = base + kboff;
#pragma unroll
        for (int kk = 0; kk < 8; kk++) {
#pragma unroll
            for (int ng = 0; ng < 4; ng++) {
                uint32_t bh4[4], bl4[4];
                const uint32_t a = kb + (uint32_t)(ng * 16 * KSP * 2) + kk * 32;
                ldm4(bh4, a);
                ldm4(bl4, a + KTILE);
                mma16816(s[2 * ng + 0], qfh[kk], bh4 + 0);
                mma16816(s[2 * ng + 0], qfl[kk], bh4 + 0);
                mma16816(s[2 * ng + 0], qfh[kk], bl4 + 0);
                mma16816(s[2 * ng + 1], qfh[kk], bh4 + 2);
                mma16816(s[2 * ng + 1], qfl[kk], bh4 + 2);
                mma16816(s[2 * ng + 1], qfh[kk], bl4 + 2);
            }
        }

        if (n0 + FBN - 1 > m0) {
#pragma unroll
            for (int j = 0; j < 8; j++) {
                const int col = n0 + j * 8 + cquad;
                if (col > r0g)         s[j][0] = -1e30f;
                if (col + 1 > r0g)     s[j][1] = -1e30f;
                if (col > r0g + 8)     s[j][2] = -1e30f;
                if (col + 1 > r0g + 8) s[j][3] = -1e30f;
            }
        }

        float mx0 = -1e30f, mx8 = -1e30f;
#pragma unroll
        for (int j = 0; j < 8; j++) {
            mx0 = fmaxf(mx0, fmaxf(s[j][0], s[j][1]));
            mx8 = fmaxf(mx8, fmaxf(s[j][2], s[j][3]));
        }
        mx0 = fmaxf(mx0, __shfl_xor_sync(0xffffffffu, mx0, 1));
        mx0 = fmaxf(mx0, __shfl_xor_sync(0xffffffffu, mx0, 2));
        mx8 = fmaxf(mx8, __shfl_xor_sync(0xffffffffu, mx8, 1));
        mx8 = fmaxf(mx8, __shfl_xor_sync(0xffffffffu, mx8, 2));

        const float mn0 = fmaxf(mrow0, mx0), mn8 = fmaxf(mrow8, mx8);
        const float sc0 = __expf(mrow0 - mn0), sc8 = __expf(mrow8 - mn8);
        mrow0 = mn0; mrow8 = mn8;

        float sum0 = 0.f, sum8 = 0.f;
        uint32_t ph[4][4], pl[4][4];
#pragma unroll
        for (int g = 0; g < 4; g++) {
#pragma unroll
            for (int jj = 0; jj < 2; jj++) {
                const int j = 2 * g + jj;
                const float e0 = __expf(s[j][0] - mn0);
                const float e1 = __expf(s[j][1] - mn0);
                const float e2 = __expf(s[j][2] - mn8);
                const float e3 = __expf(s[j][3] - mn8);
                sum0 += e0 + e1; sum8 += e2 + e3;
                bf h0 = __float2bfloat16(e0), h1 = __float2bfloat16(e1);
                bf h2 = __float2bfloat16(e2), h3 = __float2bfloat16(e3);
                ph[g][2 * jj + 0] = pack_bf(h0, h1);
                ph[g][2 * jj + 1] = pack_bf(h2, h3);
                pl[g][2 * jj + 0] = pack_bf(
                    __float2bfloat16(e0 - __bfloat162float(h0)),
                    __float2bfloat16(e1 - __bfloat162float(h1)));
                pl[g][2 * jj + 1] = pack_bf(
                    __float2bfloat16(e2 - __bfloat162float(h2)),
                    __float2bfloat16(e3 - __bfloat162float(h3)));
            }
        }
        sum0 += __shfl_xor_sync(0xffffffffu, sum0, 1);
        sum0 += __shfl_xor_sync(0xffffffffu, sum0, 2);
        sum8 += __shfl_xor_sync(0xffffffffu, sum8, 1);
        sum8 += __shfl_xor_sync(0xffffffffu, sum8, 2);
        lrow0 = lrow0 * sc0 + sum0;
        lrow8 = lrow8 * sc8 + sum8;

#pragma unroll
        for (int j = 0; j < 16; j++) {
            ctxa[j][0] *= sc0; ctxa[j][1] *= sc0;
            ctxa[j][2] *= sc8; ctxa[j][3] *= sc8;
        }

        const uint32_t vb = base + 2 * KTILE + vboff;
#pragma unroll
        for (int g = 0; g < 4; g++) {
#pragma unroll
            for (int ng = 0; ng < 8; ng++) {
                uint32_t vh4[4], vl4[4];
                const uint32_t a = vb + (uint32_t)(ng * 16 * VSP * 2) + g * 32;
                ldm4(vh4, a);
                ldm4(vl4, a + VTILE);
                mma16816(ctxa[2 * ng + 0], ph[g], vh4 + 0);
                mma16816(ctxa[2 * ng + 0], pl[g], vh4 + 0);
                mma16816(ctxa[2 * ng + 0], ph[g], vl4 + 0);
                mma16816(ctxa[2 * ng + 1], ph[g], vh4 + 2);
                mma16816(ctxa[2 * ng + 1], pl[g], vh4 + 2);
                mma16816(ctxa[2 * ng + 1], ph[g], vl4 + 2);
            }
        }
        __syncthreads();
        load_kv(i + 2);
    }

    const float inv0 = 1.0f / lrow0, inv8 = 1.0f / lrow8;
    const int r0 = m0 + w * 16 + (lane >> 2);
#pragma unroll
    for (int j = 0; j < 16; j++) {
        const int col = h * HD + j * 8 + cquad;
        const size_t i0 = ((size_t)b * SS + r0) * DOUT + col;
        const size_t i8 = ((size_t)b * SS + r0 + 8) * DOUT + col;
        split2(ctxa[j][0] * inv0, ctxa[j][1] * inv0, ctxh, ctxl, i0);
        split2(ctxa[j][2] * inv8, ctxa[j][3] * inv8, ctxh, ctxl, i8);
    }
}

// ---------------- prep kernels ----------------
__global__ void k_split(const float* __restrict__ in, bf* __restrict__ hi,
                        bf* __restrict__ lo, int n)
{
    const int i = (blockIdx.x * blockDim.x + threadIdx.x) * 2;
    if (i < n) {
        float2 v = *reinterpret_cast<const float2*>(in + i);
        split2(v.x, v.y, hi, lo, (size_t)i);
    }
}

__global__ void k_tsplit(const float* __restrict__ in, int ldin,
                         bf* __restrict__ oh, bf* __restrict__ ol, int ldout)
{
    __shared__ float t[32][33];
    const int c0 = blockIdx.x * 32, r0 = blockIdx.y * 32;
    const int tx = threadIdx.x, ty = threadIdx.y;
#pragma unroll
    for (int i = 0; i < 32; i += 8)
        t[ty + i][tx] = in[(size_t)(r0 + ty + i) * ldin + c0 + tx];
    __syncthreads();
#pragma unroll
    for (int i = 0; i < 32; i += 8) {
        const float v = t[tx][ty + i];
        const size_t idx = (size_t)(c0 + ty + i) * ldout + r0 + tx;
        bf h = __float2bfloat16(v);
        oh[idx] = h;
        ol[idx] = __float2bfloat16(v - __bfloat162float(h));
    }
}

__global__ void k_vtrans(const float* __restrict__ vp,
                         bf* __restrict__ oh, bf* __restrict__ ol)
{
    __shared__ float t[32][33];
    const int z = blockIdx.z;
    const int b = z / KVH, kv = z % KVH;
    const float* ip = vp + (size_t)b * SS * DKV + kv * HD;
    const size_t obase = (size_t)z * HD * SS;
    const int c0 = blockIdx.x * 32, r0 = blockIdx.y * 32;
    const int tx = threadIdx.x, ty = threadIdx.y;
#pragma unroll
    for (int i = 0; i < 32; i += 8)
        t[ty + i][tx] = ip[(size_t)(r0 + ty + i) * DKV + c0 + tx];
    __syncthreads();
#pragma unroll
    for (int i = 0; i < 32; i += 8) {
        const float v = t[tx][ty + i];
        const size_t idx = obase + (size_t)(c0 + ty + i) * SS + r0 + tx;
        bf h = __float2bfloat16(v);
        oh[idx] = h;
        ol[idx] = __float2bfloat16(v - __bfloat162float(h));
    }
}

// ---------------- launch ----------------
extern "C" void kernel_launch(void* const* d_in, const int* in_sizes, int n_in,
                              void* d_out, int out_size)
{
    const float* x    = (const float*)d_in[0];
    const float* cosb = (const float*)d_in[2];
    const float* sinb = (const float*)d_in[3];
    const float* Wq   = (const float*)d_in[4];
    const float* Wk   = (const float*)d_in[5];
    const float* Wv   = (const float*)d_in[6];
    const float* Wo   = (const float*)d_in[7];
    const float* qs   = (const float*)d_in[8];
    const float* ks   = (const float*)d_in[9];
    float* out = (float*)d_out;

    float* vp;
    bf *xh, *xl, *WTh, *WTl, *WoTh, *WoTl;
    bf *qhmh, *qhml, *khmh, *khml, *vTh, *vTl, *ctxh, *ctxl;
    cudaGetSymbolAddress((void**)&vp,   g_vp);
    cudaGetSymbolAddress((void**)&xh,   g_xh);
    cudaGetSymbolAddress((void**)&xl,   g_xl);
    cudaGetSymbolAddress((void**)&WTh,  g_WTh);
    cudaGetSymbolAddress((void**)&WTl,  g_WTl);
    cudaGetSymbolAddress((void**)&WoTh, g_WoTh);
    cudaGetSymbolAddress((void**)&WoTl, g_WoTl);
    cudaGetSymbolAddress((void**)&qhmh, g_qhmh);
    cudaGetSymbolAddress((void**)&qhml, g_qhml);
    cudaGetSymbolAddress((void**)&khmh, g_khmh);
    cudaGetSymbolAddress((void**)&khml, g_khml);
    cudaGetSymbolAddress((void**)&vTh,  g_vTh);
    cudaGetSymbolAddress((void**)&vTl,  g_vTl);
    cudaGetSymbolAddress((void**)&ctxh, g_ctxh);
    cudaGetSymbolAddress((void**)&ctxl, g_ctxl);

    cudaFuncSetAttribute(k_mma_dense, cudaFuncAttributeMaxDynamicSharedMemorySize, SMEM_DYN3);
    cudaFuncSetAttribute(k_mma_qkv,   cudaFuncAttributeMaxDynamicSharedMemorySize, SMEM_DYN3);
    cudaFuncSetAttribute(k_attn,      cudaFuncAttributeMaxDynamicSharedMemorySize, FSMEM);

    const dim3 tb(32, 8);

    // Prep: transpose+split weights into combined [q|k|v] buffer, split x
    k_tsplit<<<dim3(DOUT / 32, DIN / 32), tb>>>(Wq, DOUT, WTh, WTl, DIN);
    k_tsplit<<<dim3(DKV / 32, DIN / 32), tb>>>(Wk, DKV,
        WTh + (size_t)DOUT * DIN, WTl + (size_t)DOUT * DIN, DIN);
    k_tsplit<<<dim3(DKV / 32, DIN / 32), tb>>>(Wv, DKV,
        WTh + (size_t)(DOUT + DKV) * DIN, WTl + (size_t)(DOUT + DKV) * DIN, DIN);
    k_tsplit<<<dim3(DIN / 32, DOUT / 32), tb>>>(Wo, DIN, WoTh, WoTl, DOUT);
    k_split<<<(BS * DIN / 2 + 255) / 256, 256>>>(x, xh, xl, BS * DIN);

    // Merged QKV projection with fused rmsnorm+rope+split epilogue
    k_mma_qkv<<<dim3(NQKV / BN, BS / BM), NTHR, SMEM_DYN3>>>(
        xh, xl, WTh, WTl, vp, qhmh, qhml, khmh, khml, cosb, sinb, qs, ks);

    // V transpose + split
    k_vtrans<<<dim3(HD / 32, SS / 32, BB * KVH), tb>>>(vp, vTh, vTl);

    // Fused flash attention
    k_attn<<<dim3(SS / FBM, BB * NH), 256, FSMEM>>>(
        qhmh, qhml, khmh, khml, vTh, vTl, ctxh, ctxl);

    // Output projection
    k_mma_dense<<<dim3(DIN / BN, BS / BM), NTHR, SMEM_DYN3>>>(
        ctxh, ctxl, DOUT, WoTh, WoTl, DOUT, out, DIN, DOUT);
}

// round 10
// speedup vs baseline: 1.0421x; 1.0421x over previous
#include <cuda_runtime.h>
#include <cuda_bf16.h>
#include <stdint.h>
#include <math.h>

// ---------------- problem constants ----------------
#define BB   2
#define SS   2048
#define DIN  2048
#define NH   16
#define KVH  4
#define HD   128
#define GRP  (NH / KVH)            // 4
#define DOUT (NH * HD)             // 2048
#define DKV  (KVH * HD)            // 512
#define BS   (BB * SS)             // 4096
#define NQKV (DOUT + 2 * DKV)      // 3072

// ---------------- dense gemm tiling ----------------
#define BM 128
#define BN 128
#define BK 32
#define BKP 40
#define NTHR 256

#define OFF_AHI 0
#define OFF_ALO (BM * BKP * 2)
#define OFF_BHI (2 * BM * BKP * 2)
#define OFF_BLO (3 * BM * BKP * 2)
#define STAGE   (4 * BM * BKP * 2)      // 40960 B
#define SMEM_DYN (2 * STAGE)            // 81920 B  -> 2 CTAs/SM

// ---------------- fused attention tiling ----------------
#define FBM 128
#define FBN 64
#define KSP 136
#define VSP 72
#define QSP 136
#define KTILE (64 * KSP * 2)
#define VTILE (128 * VSP * 2)
#define FSTAGE (2 * KTILE + 2 * VTILE)   // 71680 B
#define FSMEM (2 * FSTAGE)               // 143360 B
#define QBYTES (128 * QSP * 2)

typedef __nv_bfloat16 bf;

// ---------------- device scratch ----------------
__device__ float g_vp [(size_t)BS * DKV];

__device__ bf g_xh [(size_t)BS * DIN],  g_xl [(size_t)BS * DIN];
__device__ bf g_WTh[(size_t)NQKV * DIN], g_WTl[(size_t)NQKV * DIN]; // q|k|v rows
__device__ bf g_WoTh[(size_t)DIN * DOUT], g_WoTl[(size_t)DIN * DOUT];
__device__ bf g_qhmh[(size_t)BS * DOUT],  g_qhml[(size_t)BS * DOUT];
__device__ bf g_khmh[(size_t)BS * DKV],   g_khml[(size_t)BS * DKV];
__device__ bf g_vTh [(size_t)BB * KVH * HD * SS], g_vTl[(size_t)BB * KVH * HD * SS];
__device__ bf g_ctxh[(size_t)BS * DOUT],  g_ctxl[(size_t)BS * DOUT];

// ---------------- helpers ----------------
__device__ __forceinline__ uint32_t smem_u32(const void* p) {
    uint32_t a;
    asm("{ .reg .u64 t; cvta.to.shared.u64 t, %1; cvt.u32.u64 %0, t; }"
        : "=r"(a) : "l"(p));
    return a;
}
__device__ __forceinline__ uint32_t pack_bf(bf a, bf b) {
    uint16_t ua = *reinterpret_cast<uint16_t*>(&a);
    uint16_t ub = *reinterpret_cast<uint16_t*>(&b);
    return (uint32_t)ua | ((uint32_t)ub << 16);
}
__device__ __forceinline__ void split2(float x, float y, bf* hi, bf* lo,
                                       size_t idx) {
    bf h0 = __float2bfloat16(x), h1 = __float2bfloat16(y);
    bf l0 = __float2bfloat16(x - __bfloat162float(h0));
    bf l1 = __float2bfloat16(y - __bfloat162float(h1));
    *reinterpret_cast<uint32_t*>(hi + idx) = pack_bf(h0, h1);
    *reinterpret_cast<uint32_t*>(lo + idx) = pack_bf(l0, l1);
}
__device__ __forceinline__ void cpasync16(uint32_t dst, const void* src) {
    asm volatile("cp.async.cg.shared.global [%0], [%1], 16;"
                 :: "r"(dst), "l"(src));
}
__device__ __forceinline__ void ldm4(uint32_t* d, uint32_t addr) {
    asm volatile("ldmatrix.sync.aligned.m8n8.x4.shared.b16 {%0,%1,%2,%3}, [%4];"
                 : "=r"(d[0]), "=r"(d[1]), "=r"(d[2]), "=r"(d[3]) : "r"(addr));
}
__device__ __forceinline__ void mma16816(float* c, const uint32_t* a, const uint32_t* b) {
    asm volatile(
        "mma.sync.aligned.m16n8k16.row.col.f32.bf16.bf16.f32 "
        "{%0,%1,%2,%3}, {%4,%5,%6,%7}, {%8,%9}, {%0,%1,%2,%3};"
        : "+f"(c[0]), "+f"(c[1]), "+f"(c[2]), "+f"(c[3])
        : "r"(a[0]), "r"(a[1]), "r"(a[2]), "r"(a[3]), "r"(b[0]), "r"(b[1]));
}

// ---------------- 2-stage pipelined HMMA bf16x3 NT compute ----------------
// acc = A[m0:+128, 0:kmax] @ B[n0:+128, 0:kmax]^T   (per-thread fragments)
__device__ __forceinline__ void mma_compute(
    char* dyn,
    const bf* __restrict__ Ahi, const bf* __restrict__ Alo, int lda,
    const bf* __restrict__ Bhi, const bf* __restrict__ Blo, int ldb,
    int kmax, int m0, int n0, float acc[4][4][4])
{
    const int tid  = threadIdx.x;
    const int lane = tid & 31;
    const int wid  = tid >> 5;
    const int wm   = wid & 1;
    const int wn   = wid >> 1;
    const uint32_t sb = smem_u32(dyn);

#pragma unroll
    for (int i = 0; i < 4; i++)
#pragma unroll
        for (int j = 0; j < 4; j++)
#pragma unroll
            for (int k = 0; k < 4; k++) acc[i][j][k] = 0.f;

    const uint32_t aoff =
        (uint32_t)(((wm * 64 + (lane & 15)) * BKP + ((lane >> 4) * 8)) * 2);
    const uint32_t boff =
        (uint32_t)(((wn * 32 + ((lane >> 4) * 8) + (lane & 7)) * BKP +
                    (((lane >> 3) & 1) * 8)) * 2);

    const int frow = tid >> 2;
    const int fkg  = (tid & 3) * 8;
    const int nch = kmax / BK;

#pragma unroll
    for (int i = 0; i < 2; i++) {
        const int row = frow + i * 64;
        const uint32_t so = (uint32_t)(row * BKP + fkg) * 2;
        const size_t ai = (size_t)(m0 + row) * lda + fkg;
        const size_t bi = (size_t)(n0 + row) * ldb + fkg;
        cpasync16(sb + OFF_AHI + so, Ahi + ai);
        cpasync16(sb + OFF_ALO + so, Alo + ai);
        cpasync16(sb + OFF_BHI + so, Bhi + bi);
        cpasync16(sb + OFF_BLO + so, Blo + bi);
    }
    asm volatile("cp.async.commit_group;");

    for (int ch = 0; ch < nch; ch++) {
        const uint32_t base = sb + (uint32_t)(ch & 1) * STAGE;
        if (ch + 1 < nch) {
            const uint32_t nb2 = sb + (uint32_t)((ch + 1) & 1) * STAGE;
            const int k0 = (ch + 1) * BK;
#pragma unroll
            for (int i = 0; i < 2; i++) {
                const int row = frow + i * 64;
                const uint32_t so = (uint32_t)(row * BKP + fkg) * 2;
                const size_t ai = (size_t)(m0 + row) * lda + k0 + fkg;
                const size_t bi = (size_t)(n0 + row) * ldb + k0 + fkg;
                cpasync16(nb2 + OFF_AHI + so, Ahi + ai);
                cpasync16(nb2 + OFF_ALO + so, Alo + ai);
                cpasync16(nb2 + OFF_BHI + so, Bhi + bi);
                cpasync16(nb2 + OFF_BLO + so, Blo + bi);
            }
            asm volatile("cp.async.commit_group;");
            asm volatile("cp.async.wait_group 1;");
        } else {
            asm volatile("cp.async.wait_group 0;");
        }
        __syncthreads();

        const uint32_t aHi = base + OFF_AHI + aoff;
        const uint32_t aLo = base + OFF_ALO + aoff;
        const uint32_t bHi = base + OFF_BHI + boff;
        const uint32_t bLo = base + OFF_BLO + boff;
#pragma unroll
        for (int ks = 0; ks < 2; ks++) {
            uint32_t bh[8], bl[8];
            ldm4(bh + 0, bHi + ks * 32);
            ldm4(bh + 4, bHi + 16 * BKP * 2 + ks * 32);
            ldm4(bl + 0, bLo + ks * 32);
            ldm4(bl + 4, bLo + 16 * BKP * 2 + ks * 32);
#pragma unroll
            for (int mt = 0; mt < 4; mt++) {
                uint32_t ah[4], al[4];
                ldm4(ah, aHi + mt * 16 * BKP * 2 + ks * 32);
                ldm4(al, aLo + mt * 16 * BKP * 2 + ks * 32);
#pragma unroll
                for (int nt = 0; nt < 4; nt++) {
                    mma16816(acc[mt][nt], ah, &bh[nt * 2]);
                    mma16816(acc[mt][nt], al, &bh[nt * 2]);
                    mma16816(acc[mt][nt], ah, &bl[nt * 2]);
                }
            }
        }
        __syncthreads();
    }
}

// ---------------- O-projection GEMM (plain fp32 epilogue) ----------------
__global__ void __launch_bounds__(NTHR)
k_mma_dense(const bf* __restrict__ Ahi, const bf* __restrict__ Alo, int lda,
            const bf* __restrict__ Bhi, const bf* __restrict__ Blo, int ldb,
            float* __restrict__ C, int ldc, int K)
{
    extern __shared__ char dyn[];
    const int m0 = blockIdx.y * BM, n0 = blockIdx.x * BN;
    float acc[4][4][4];
    mma_compute(dyn, Ahi, Alo, lda, Bhi, Blo, ldb, K, m0, n0, acc);

    const int lane = threadIdx.x & 31, wid = threadIdx.x >> 5;
    const int wm = wid & 1, wn = wid >> 1;
#pragma unroll
    for (int mt = 0; mt < 4; mt++)
#pragma unroll
        for (int half = 0; half < 2; half++) {
            const int row = m0 + wm * 64 + mt * 16 + (lane >> 2) + half * 8;
#pragma unroll
            for (int nt = 0; nt < 4; nt++) {
                const int col = n0 + wn * 32 + nt * 8 + (lane & 3) * 2;
                *reinterpret_cast<float2*>(C + (size_t)row * ldc + col) =
                    make_float2(acc[mt][nt][half * 2 + 0],
                                acc[mt][nt][half * 2 + 1]);
            }
        }
}

// ---------------- merged QKV GEMM + fused rmsnorm/rope/split epilogue ----
__global__ void __launch_bounds__(NTHR)
k_mma_qkv(const bf* __restrict__ xh, const bf* __restrict__ xl,
          const bf* __restrict__ Wh, const bf* __restrict__ Wl,
          float* __restrict__ vp,
          bf* __restrict__ qhmh, bf* __restrict__ qhml,
          bf* __restrict__ khmh, bf* __restrict__ khml,
          const float* __restrict__ cosb, const float* __restrict__ sinb,
          const float* __restrict__ qs, const float* __restrict__ ks)
{
    extern __shared__ char dyn[];
    const int m0 = blockIdx.y * BM, n0 = blockIdx.x * BN;
    float acc[4][4][4];
    mma_compute(dyn, xh, xl, DIN, Wh, Wl, DIN, DIN, m0, n0, acc);

    const int lane = threadIdx.x & 31, wid = threadIdx.x >> 5;
    const int wm = wid & 1, wn = wid >> 1;

    if (n0 >= DOUT + DKV) {
        // ---- V tile: plain fp32 store (vtrans consumes) ----
        const int coff = n0 - DOUT - DKV;
#pragma unroll
        for (int mt = 0; mt < 4; mt++)
#pragma unroll
            for (int half = 0; half < 2; half++) {
                const int row = m0 + wm * 64 + mt * 16 + (lane >> 2) + half * 8;
#pragma unroll
                for (int nt = 0; nt < 4; nt++) {
                    const int col = coff + wn * 32 + nt * 8 + (lane & 3) * 2;
                    *reinterpret_cast<float2*>(vp + (size_t)row * DKV + col) =
                        make_float2(acc[mt][nt][half * 2 + 0],
                                    acc[mt][nt][half * 2 + 1]);
                }
            }
        return;
    }

    // ---- Q/K tile: rmsnorm + rope + split, head-major output ----
    const bool isQ = (n0 < DOUT);
    const float* scale = isQ ? qs : ks;
    bf* oh = isQ ? qhmh : khmh;
    bf* ol = isQ ? qhml : khml;
    const int nheads = isQ ? NH : KVH;
    const int h = (isQ ? n0 : (n0 - DOUT)) / HD;
    const float alpha = isQ ? 0.08838834764831845f : 1.0f;

    float* rsum = reinterpret_cast<float*>(dyn);                 // [128][4]
    float* stg  = reinterpret_cast<float*>(dyn + 2048);          // [128][132]

    // 1) partial sum of squares per row (32 cols per warp)
#pragma unroll
    for (int mt = 0; mt < 4; mt++)
#pragma unroll
        for (int half = 0; half < 2; half++) {
            const int rl = wm * 64 + mt * 16 + (lane >> 2) + half * 8;
            float part = 0.f;
#pragma unroll
            for (int nt = 0; nt < 4; nt++) {
                const float vx = acc[mt][nt][half * 2 + 0];
                const float vy = acc[mt][nt][half * 2 + 1];
                part += vx * vx + vy * vy;
            }
            part += __shfl_xor_sync(0xffffffffu, part, 1);
            part += __shfl_xor_sync(0xffffffffu, part, 2);
            if ((lane & 3) == 0) rsum[rl * 4 + wn] = part;
        }
    __syncthreads();

    // 2) normalize + scale into smem staging tile
#pragma unroll
    for (int mt = 0; mt < 4; mt++)
#pragma unroll
        for (int half = 0; half < 2; half++) {
            const int rl = wm * 64 + mt * 16 + (lane >> 2) + half * 8;
            const float tot = rsum[rl * 4 + 0] + rsum[rl * 4 + 1] +
                              rsum[rl * 4 + 2] + rsum[rl * 4 + 3];
            const float rinv = rsqrtf(tot * (1.0f / HD) + 1e-6f) * alpha;
#pragma unroll
            for (int nt = 0; nt < 4; nt++) {
                const int c = wn * 32 + nt * 8 + (lane & 3) * 2;
                stg[rl * 132 + c]     = acc[mt][nt][half * 2 + 0] * rinv * scale[c];
                stg[rl * 132 + c + 1] = acc[mt][nt][half * 2 + 1] * rinv * scale[c + 1];
            }
        }
    __syncthreads();

    // 3) rope + split-store head-major
#pragma unroll
    for (int mt = 0; mt < 4; mt++)
#pragma unroll
        for (int half = 0; half < 2; half++) {
            const int rl = wm * 64 + mt * 16 + (lane >> 2) + half * 8;
            const int row = m0 + rl;
            const int b = row >> 11, pos = row & (SS - 1);
#pragma unroll
            for (int nt = 0; nt < 4; nt++) {
                const int c = wn * 32 + nt * 8 + (lane & 3) * 2;
                const float xn0 = stg[rl * 132 + c];
                const float xn1 = stg[rl * 132 + c + 1];
                const int p = (c + 64) & 127;
                const float s0 = stg[rl * 132 + p];
                const float s1 = stg[rl * 132 + p + 1];
                const float rot0 = (c < 64) ? -s0 : s0;
                const float rot1 = (c < 64) ? -s1 : s1;
                const float o0 = xn0 * cosb[pos * HD + c]     + rot0 * sinb[pos * HD + c];
                const float o1 = xn1 * cosb[pos * HD + c + 1] + rot1 * sinb[pos * HD + c + 1];
                const size_t oi = ((size_t)(b * nheads + h) * SS + pos) * HD + c;
                split2(o0, o1, oh, ol, oi);
            }
        }
}

// ---------------- fused flash attention (bf16x3 HMMA) ----------------
__global__ void __launch_bounds__(256, 1)
k_attn(const bf* __restrict__ qhp, const bf* __restrict__ qlp,
       const bf* __restrict__ khp, const bf* __restrict__ klp,
       const bf* __restrict__ vhp, const bf* __restrict__ vlp,
       bf* __restrict__ ctxh, bf* __restrict__ ctxl)
{
    extern __shared__ char dyn[];
    const uint32_t sb = smem_u32(dyn);
    const int tid = threadIdx.x, lane = tid & 31, w = tid >> 5;
    const int bh = blockIdx.y, b = bh / NH, h = bh % NH;
    const int kvh = (bh % NH) / GRP;
    const int m0 = ((int)gridDim.x - 1 - (int)blockIdx.x) * FBM;
    const size_t qo = (size_t)bh * SS * HD;
    const size_t ko = (size_t)(b * KVH + kvh) * SS * HD;
    const size_t vo = (size_t)(b * KVH + kvh) * HD * SS;

#pragma unroll
    for (int it = 0; it < 8; it++) {
        const int c = tid + it * 256;
        const int row = c >> 4, col = (c & 15) * 8;
        const size_t gi = qo + (size_t)(m0 + row) * HD + col;
        cpasync16(sb + (uint32_t)(row * QSP + col) * 2, qhp + gi);
        cpasync16(sb + QBYTES + (uint32_t)(row * QSP + col) * 2, qlp + gi);
    }
    asm volatile("cp.async.commit_group;");
    asm volatile("cp.async.wait_group 0;");
    __syncthreads();

    uint32_t qfh[8][4], qfl[8][4];
    {
        const uint32_t ab = sb +
            (uint32_t)(((w * 16 + (lane & 15)) * QSP + (lane >> 4) * 8) * 2);
#pragma unroll
        for (int kk = 0; kk < 8; kk++) {
            ldm4(qfh[kk], ab + kk * 32);
            ldm4(qfl[kk], ab + QBYTES + kk * 32);
        }
    }
    __syncthreads();

    const int nb = m0 / FBN + 2;

    auto load_kv = [&](int i) {
        if (i < nb) {
            const int n0 = i * FBN;
            const uint32_t bufb = sb + (uint32_t)(i & 1) * FSTAGE;
#pragma unroll
            for (int it = 0; it < 4; it++) {
                const int c = tid + it * 256;
                const int krow = c >> 4, kcol = (c & 15) * 8;
                const size_t gk = ko + (size_t)(n0 + krow) * HD + kcol;
                cpasync16(bufb + (uint32_t)(krow * KSP + kcol) * 2, khp + gk);
                cpasync16(bufb + KTILE + (uint32_t)(krow * KSP + kcol) * 2, klp + gk);
                const int vrow = c >> 3, vcol = (c & 7) * 8;
                const size_t gv = vo + (size_t)vrow * SS + n0 + vcol;
                cpasync16(bufb + 2 * KTILE + (uint32_t)(vrow * VSP + vcol) * 2, vhp + gv);
                cpasync16(bufb + 2 * KTILE + VTILE + (uint32_t)(vrow * VSP + vcol) * 2, vlp + gv);
            }
        }
        asm volatile("cp.async.commit_group;");
    };

    load_kv(0);
    load_kv(1);

    float ctxa[16][4];
#pragma unroll
    for (int j = 0; j < 16; j++)
#pragma unroll
        for (int e = 0; e < 4; e++) ctxa[j][e] = 0.f;
    float mrow0 = -1e30f, mrow8 = -1e30f, lrow0 = 0.f, lrow8 = 0.f;

    const uint32_t kboff =
        (uint32_t)((((lane >> 4) * 8 + (lane & 7)) * KSP + ((lane >> 3) & 1) * 8) * 2);
    const uint32_t vboff =
        (uint32_t)((((lane >> 4) * 8 + (lane & 7)) * VSP + ((lane >> 3) & 1) * 8) * 2);
    const int r0g = m0 + w * 16 + (lane >> 2);
    const int cquad = 2 * (lane & 3);

    for (int i = 0; i < nb; i++) {
        asm volatile("cp.async.wait_group 1;");
        __syncthreads();
        const uint32_t base = sb + (uint32_t)(i & 1) * FSTAGE;
        const int n0 = i * FBN;

        float s[8][4];
#pragma unroll
        for (int j = 0; j < 8; j++)
#pragma unroll
            for (int e = 0; e < 4; e++) s[j][e] = 0.f;

        const uint32_t kb = base + kboff;
#pragma unroll
        for (int kk = 0; kk < 8; kk++) {
#pragma unroll
            for (int ng = 0; ng < 4; ng++) {
                uint32_t bh4[4], bl4[4];
                const uint32_t a = kb + (uint32_t)(ng * 16 * KSP * 2) + kk * 32;
                ldm4(bh4, a);
                ldm4(bl4, a + KTILE);
                mma16816(s[2 * ng + 0], qfh[kk], bh4 + 0);
                mma16816(s[2 * ng + 0], qfl[kk], bh4 + 0);
                mma16816(s[2 * ng + 0], qfh[kk], bl4 + 0);
                mma16816(s[2 * ng + 1], qfh[kk], bh4 + 2);
                mma16816(s[2 * ng + 1], qfl[kk], bh4 + 2);
                mma16816(s[2 * ng + 1], qfh[kk], bl4 + 2);
            }
        }

        if (n0 + FBN - 1 > m0) {
#pragma unroll
            for (int j = 0; j < 8; j++) {
                const int col = n0 + j * 8 + cquad;
                if (col > r0g)         s[j][0] = -1e30f;
                if (col + 1 > r0g)     s[j][1] = -1e30f;
                if (col > r0g + 8)     s[j][2] = -1e30f;
                if (col + 1 > r0g + 8) s[j][3] = -1e30f;
            }
        }

        float mx0 = -1e30f, mx8 = -1e30f;
#pragma unroll
        for (int j = 0; j < 8; j++) {
            mx0 = fmaxf(mx0, fmaxf(s[j][0], s[j][1]));
            mx8 = fmaxf(mx8, fmaxf(s[j][2], s[j][3]));
        }
        mx0 = fmaxf(mx0, __shfl_xor_sync(0xffffffffu, mx0, 1));
        mx0 = fmaxf(mx0, __shfl_xor_sync(0xffffffffu, mx0, 2));
        mx8 = fmaxf(mx8, __shfl_xor_sync(0xffffffffu, mx8, 1));
        mx8 = fmaxf(mx8, __shfl_xor_sync(0xffffffffu, mx8, 2));

        const float mn0 = fmaxf(mrow0, mx0), mn8 = fmaxf(mrow8, mx8);
        const float sc0 = __expf(mrow0 - mn0), sc8 = __expf(mrow8 - mn8);
        mrow0 = mn0; mrow8 = mn8;

        float sum0 = 0.f, sum8 = 0.f;
        uint32_t ph[4][4], pl[4][4];
#pragma unroll
        for (int g = 0; g < 4; g++) {
#pragma unroll
            for (int jj = 0; jj < 2; jj++) {
                const int j = 2 * g + jj;
                const float e0 = __expf(s[j][0] - mn0);
                const float e1 = __expf(s[j][1] - mn0);
                const float e2 = __expf(s[j][2] - mn8);
                const float e3 = __expf(s[j][3] - mn8);
                sum0 += e0 + e1; sum8 += e2 + e3;
                bf h0 = __float2bfloat16(e0), h1 = __float2bfloat16(e1);
                bf h2 = __float2bfloat16(e2), h3 = __float2bfloat16(e3);
                ph[g][2 * jj + 0] = pack_bf(h0, h1);
                ph[g][2 * jj + 1] = pack_bf(h2, h3);
                pl[g][2 * jj + 0] = pack_bf(
                    __float2bfloat16(e0 - __bfloat162float(h0)),
                    __float2bfloat16(e1 - __bfloat162float(h1)));
                pl[g][2 * jj + 1] = pack_bf(
                    __float2bfloat16(e2 - __bfloat162float(h2)),
                    __float2bfloat16(e3 - __bfloat162float(h3)));
            }
        }
        sum0 += __shfl_xor_sync(0xffffffffu, sum0, 1);
        sum0 += __shfl_xor_sync(0xffffffffu, sum0, 2);
        sum8 += __shfl_xor_sync(0xffffffffu, sum8, 1);
        sum8 += __shfl_xor_sync(0xffffffffu, sum8, 2);
        lrow0 = lrow0 * sc0 + sum0;
        lrow8 = lrow8 * sc8 + sum8;

#pragma unroll
        for (int j = 0; j < 16; j++) {
            ctxa[j][0] *= sc0; ctxa[j][1] *= sc0;
            ctxa[j][2] *= sc8; ctxa[j][3] *= sc8;
        }

        const uint32_t vb = base + 2 * KTILE + vboff;
#pragma unroll
        for (int g = 0; g < 4; g++) {
#pragma unroll
            for (int ng = 0; ng < 8; ng++) {
                uint32_t vh4[4], vl4[4];
                const uint32_t a = vb + (uint32_t)(ng * 16 * VSP * 2) + g * 32;
                ldm4(vh4, a);
                ldm4(vl4, a + VTILE);
                mma16816(ctxa[2 * ng + 0], ph[g], vh4 + 0);
                mma16816(ctxa[2 * ng + 0], pl[g], vh4 + 0);
                mma16816(ctxa[2 * ng + 0], ph[g], vl4 + 0);
                mma16816(ctxa[2 * ng + 1], ph[g], vh4 + 2);
                mma16816(ctxa[2 * ng + 1], pl[g], vh4 + 2);
                mma16816(ctxa[2 * ng + 1], ph[g], vl4 + 2);
            }
        }
        __syncthreads();
        load_kv(i + 2);
    }

    const float inv0 = 1.0f / lrow0, inv8 = 1.0f / lrow8;
    const int r0 = m0 + w * 16 + (lane >> 2);
#pragma unroll
    for (int j = 0; j < 16; j++) {
        const int col = h * HD + j * 8 + cquad;
        const size_t i0 = ((size_t)b * SS + r0) * DOUT + col;
        const size_t i8 = ((size_t)b * SS + r0 + 8) * DOUT + col;
        split2(ctxa[j][0] * inv0, ctxa[j][1] * inv0, ctxh, ctxl, i0);
        split2(ctxa[j][2] * inv8, ctxa[j][3] * inv8, ctxh, ctxl, i8);
    }
}

// ---------------- prep kernels ----------------
__global__ void k_split(const float* __restrict__ in, bf* __restrict__ hi,
                        bf* __restrict__ lo, int n)
{
    const int i = (blockIdx.x * blockDim.x + threadIdx.x) * 2;
    if (i < n) {
        float2 v = *reinterpret_cast<const float2*>(in + i);
        split2(v.x, v.y, hi, lo, (size_t)i);
    }
}

__global__ void k_tsplit(const float* __restrict__ in, int ldin,
                         bf* __restrict__ oh, bf* __restrict__ ol, int ldout)
{
    __shared__ float t[32][33];
    const int c0 = blockIdx.x * 32, r0 = blockIdx.y * 32;
    const int tx = threadIdx.x, ty = threadIdx.y;
#pragma unroll
    for (int i = 0; i < 32; i += 8)
        t[ty + i][tx] = in[(size_t)(r0 + ty + i) * ldin + c0 + tx];
    __syncthreads();
#pragma unroll
    for (int i = 0; i < 32; i += 8) {
        const float v = t[tx][ty + i];
        const size_t idx = (size_t)(c0 + ty + i) * ldout + r0 + tx;
        bf h = __float2bfloat16(v);
        oh[idx] = h;
        ol[idx] = __float2bfloat16(v - __bfloat162float(h));
    }
}

__global__ void k_vtrans(const float* __restrict__ vp,
                         bf* __restrict__ oh, bf* __restrict__ ol)
{
    __shared__ float t[32][33];
    const int z = blockIdx.z;
    const int b = z / KVH, kv = z % KVH;
    const float* ip = vp + (size_t)b * SS * DKV + kv * HD;
    const size_t obase = (size_t)z * HD * SS;
    const int c0 = blockIdx.x * 32, r0 = blockIdx.y * 32;
    const int tx = threadIdx.x, ty = threadIdx.y;
#pragma unroll
    for (int i = 0; i < 32; i += 8)
        t[ty + i][tx] = ip[(size_t)(r0 + ty + i) * DKV + c0 + tx];
    __syncthreads();
#pragma unroll
    for (int i = 0; i < 32; i += 8) {
        const float v = t[tx][ty + i];
        const size_t idx = obase + (size_t)(c0 + ty + i) * SS + r0 + tx;
        bf h = __float2bfloat16(v);
        oh[idx] = h;
        ol[idx] = __float2bfloat16(v - __bfloat162float(h));
    }
}

// ---------------- launch ----------------
extern "C" void kernel_launch(void* const* d_in, const int* in_sizes, int n_in,
                              void* d_out, int out_size)
{
    const float* x    = (const float*)d_in[0];
    const float* cosb = (const float*)d_in[2];
    const float* sinb = (const float*)d_in[3];
    const float* Wq   = (const float*)d_in[4];
    const float* Wk   = (const float*)d_in[5];
    const float* Wv   = (const float*)d_in[6];
    const float* Wo   = (const float*)d_in[7];
    const float* qs   = (const float*)d_in[8];
    const float* ks   = (const float*)d_in[9];
    float* out = (float*)d_out;

    float* vp;
    bf *xh, *xl, *WTh, *WTl, *WoTh, *WoTl;
    bf *qhmh, *qhml, *khmh, *khml, *vTh, *vTl, *ctxh, *ctxl;
    cudaGetSymbolAddress((void**)&vp,   g_vp);
    cudaGetSymbolAddress((void**)&xh,   g_xh);
    cudaGetSymbolAddress((void**)&xl,   g_xl);
    cudaGetSymbolAddress((void**)&WTh,  g_WTh);
    cudaGetSymbolAddress((void**)&WTl,  g_WTl);
    cudaGetSymbolAddress((void**)&WoTh, g_WoTh);
    cudaGetSymbolAddress((void**)&WoTl, g_WoTl);
    cudaGetSymbolAddress((void**)&qhmh, g_qhmh);
    cudaGetSymbolAddress((void**)&qhml, g_qhml);
    cudaGetSymbolAddress((void**)&khmh, g_khmh);
    cudaGetSymbolAddress((void**)&khml, g_khml);
    cudaGetSymbolAddress((void**)&vTh,  g_vTh);
    cudaGetSymbolAddress((void**)&vTl,  g_vTl);
    cudaGetSymbolAddress((void**)&ctxh, g_ctxh);
    cudaGetSymbolAddress((void**)&ctxl, g_ctxl);

    cudaFuncSetAttribute(k_mma_dense, cudaFuncAttributeMaxDynamicSharedMemorySize, SMEM_DYN);
    cudaFuncSetAttribute(k_mma_qkv,   cudaFuncAttributeMaxDynamicSharedMemorySize, SMEM_DYN);
    cudaFuncSetAttribute(k_attn,      cudaFuncAttributeMaxDynamicSharedMemorySize, FSMEM);

    const dim3 tb(32, 8);

    // Prep: transpose+split weights into combined [q|k|v] buffer, split x
    k_tsplit<<<dim3(DOUT / 32, DIN / 32), tb>>>(Wq, DOUT, WTh, WTl, DIN);
    k_tsplit<<<dim3(DKV / 32, DIN / 32), tb>>>(Wk, DKV,
        WTh + (size_t)DOUT * DIN, WTl + (size_t)DOUT * DIN, DIN);
    k_tsplit<<<dim3(DKV / 32, DIN / 32), tb>>>(Wv, DKV,
        WTh + (size_t)(DOUT + DKV) * DIN, WTl + (size_t)(DOUT + DKV) * DIN, DIN);
    k_tsplit<<<dim3(DIN / 32, DOUT / 32), tb>>>(Wo, DIN, WoTh, WoTl, DOUT);
    k_split<<<(BS * DIN / 2 + 255) / 256, 256>>>(x, xh, xl, BS * DIN);

    // Merged QKV projection with fused rmsnorm+rope+split epilogue
    k_mma_qkv<<<dim3(NQKV / BN, BS / BM), NTHR, SMEM_DYN>>>(
        xh, xl, WTh, WTl, vp, qhmh, qhml, khmh, khml, cosb, sinb, qs, ks);

    // V transpose + split
    k_vtrans<<<dim3(HD / 32, SS / 32, BB * KVH), tb>>>(vp, vTh, vTl);

    // Fused flash attention
    k_attn<<<dim3(SS / FBM, BB * NH), 256, FSMEM>>>(
        qhmh, qhml, khmh, khml, vTh, vTl, ctxh, ctxl);

    // Output projection
    k_mma_dense<<<dim3(DIN / BN, BS / BM), NTHR, SMEM_DYN>>>(
        ctxh, ctxl, DOUT, WoTh, WoTl, DOUT, out, DIN, DOUT);
}

// round 11
// speedup vs baseline: 1.1237x; 1.0782x over previous
#include <cuda_runtime.h>
#include <cuda_bf16.h>
#include <stdint.h>
#include <math.h>

// ---------------- problem constants ----------------
#define BB   2
#define SS   2048
#define DIN  2048
#define NH   16
#define KVH  4
#define HD   128
#define GRP  (NH / KVH)            // 4
#define DOUT (NH * HD)             // 2048
#define DKV  (KVH * HD)            // 512
#define BS   (BB * SS)             // 4096
#define NQKV (DOUT + 2 * DKV)      // 3072

// ---------------- dense gemm tiling (bf16x3) ----------------
#define BM 128
#define BN 128
#define BK 32
#define BKP 40
#define NTHR 256

#define OFF_AHI 0
#define OFF_ALO (BM * BKP * 2)
#define OFF_BHI (2 * BM * BKP * 2)
#define OFF_BLO (3 * BM * BKP * 2)
#define STAGE   (4 * BM * BKP * 2)      // 40960 B
#define SMEM_DYN (2 * STAGE)            // 81920 B  -> 2 CTAs/SM

// ---------------- tf32 O-proj tiling ----------------
#define OKP   36                         // fp32 row stride (floats)
#define OTILE (128 * OKP * 4)            // 18432 B per operand tile
#define OSTAGE (2 * OTILE)               // 36864 B
#define OSMEM (2 * OSTAGE)               // 73728 B -> 2 CTAs/SM

// ---------------- fused attention tiling ----------------
#define FBM 128
#define FBN 64
#define KSP 136
#define VSP 72
#define QSP 136
#define KTILE (64 * KSP * 2)
#define VTILE (128 * VSP * 2)
#define FSTAGE (2 * KTILE + 2 * VTILE)   // 71680 B
#define FSMEM (2 * FSTAGE)               // 143360 B
#define QBYTES (128 * QSP * 2)

typedef __nv_bfloat16 bf;

// ---------------- device scratch ----------------
__device__ float g_vp  [(size_t)BS * DKV];
__device__ float g_ctxf[(size_t)BS * DOUT];          // tf32-rounded fp32
__device__ float g_WoT [(size_t)DIN * DOUT];         // tf32-rounded fp32

__device__ bf g_xh [(size_t)BS * DIN],  g_xl [(size_t)BS * DIN];
__device__ bf g_WTh[(size_t)NQKV * DIN], g_WTl[(size_t)NQKV * DIN]; // q|k|v rows
__device__ bf g_qhmh[(size_t)BS * DOUT],  g_qhml[(size_t)BS * DOUT];
__device__ bf g_khmh[(size_t)BS * DKV],   g_khml[(size_t)BS * DKV];
__device__ bf g_vTh [(size_t)BB * KVH * HD * SS], g_vTl[(size_t)BB * KVH * HD * SS];

// ---------------- helpers ----------------
__device__ __forceinline__ uint32_t smem_u32(const void* p) {
    uint32_t a;
    asm("{ .reg .u64 t; cvta.to.shared.u64 t, %1; cvt.u32.u64 %0, t; }"
        : "=r"(a) : "l"(p));
    return a;
}
__device__ __forceinline__ uint32_t pack_bf(bf a, bf b) {
    uint16_t ua = *reinterpret_cast<uint16_t*>(&a);
    uint16_t ub = *reinterpret_cast<uint16_t*>(&b);
    return (uint32_t)ua | ((uint32_t)ub << 16);
}
__device__ __forceinline__ void split2(float x, float y, bf* hi, bf* lo,
                                       size_t idx) {
    bf h0 = __float2bfloat16(x), h1 = __float2bfloat16(y);
    bf l0 = __float2bfloat16(x - __bfloat162float(h0));
    bf l1 = __float2bfloat16(y - __bfloat162float(h1));
    *reinterpret_cast<uint32_t*>(hi + idx) = pack_bf(h0, h1);
    *reinterpret_cast<uint32_t*>(lo + idx) = pack_bf(l0, l1);
}
__device__ __forceinline__ float tf32r(float x) {
    float y;
    asm("cvt.rna.tf32.f32 %0, %1;" : "=f"(y) : "f"(x));
    return y;
}
__device__ __forceinline__ void cpasync16(uint32_t dst, const void* src) {
    asm volatile("cp.async.cg.shared.global [%0], [%1], 16;"
                 :: "r"(dst), "l"(src));
}
__device__ __forceinline__ void ldm4(uint32_t* d, uint32_t addr) {
    asm volatile("ldmatrix.sync.aligned.m8n8.x4.shared.b16 {%0,%1,%2,%3}, [%4];"
                 : "=r"(d[0]), "=r"(d[1]), "=r"(d[2]), "=r"(d[3]) : "r"(addr));
}
__device__ __forceinline__ void mma16816(float* c, const uint32_t* a, const uint32_t* b) {
    asm volatile(
        "mma.sync.aligned.m16n8k16.row.col.f32.bf16.bf16.f32 "
        "{%0,%1,%2,%3}, {%4,%5,%6,%7}, {%8,%9}, {%0,%1,%2,%3};"
        : "+f"(c[0]), "+f"(c[1]), "+f"(c[2]), "+f"(c[3])
        : "r"(a[0]), "r"(a[1]), "r"(a[2]), "r"(a[3]), "r"(b[0]), "r"(b[1]));
}
__device__ __forceinline__ void mma1688tf32(float* c, const uint32_t* a, const uint32_t* b) {
    asm volatile(
        "mma.sync.aligned.m16n8k8.row.col.f32.tf32.tf32.f32 "
        "{%0,%1,%2,%3}, {%4,%5,%6,%7}, {%8,%9}, {%0,%1,%2,%3};"
        : "+f"(c[0]), "+f"(c[1]), "+f"(c[2]), "+f"(c[3])
        : "r"(a[0]), "r"(a[1]), "r"(a[2]), "r"(a[3]), "r"(b[0]), "r"(b[1]));
}

// ---------------- 2-stage pipelined HMMA bf16x3 NT compute ----------------
__device__ __forceinline__ void mma_compute(
    char* dyn,
    const bf* __restrict__ Ahi, const bf* __restrict__ Alo, int lda,
    const bf* __restrict__ Bhi, const bf* __restrict__ Blo, int ldb,
    int kmax, int m0, int n0, float acc[4][4][4])
{
    const int tid  = threadIdx.x;
    const int lane = tid & 31;
    const int wid  = tid >> 5;
    const int wm   = wid & 1;
    const int wn   = wid >> 1;
    const uint32_t sb = smem_u32(dyn);

#pragma unroll
    for (int i = 0; i < 4; i++)
#pragma unroll
        for (int j = 0; j < 4; j++)
#pragma unroll
            for (int k = 0; k < 4; k++) acc[i][j][k] = 0.f;

    const uint32_t aoff =
        (uint32_t)(((wm * 64 + (lane & 15)) * BKP + ((lane >> 4) * 8)) * 2);
    const uint32_t boff =
        (uint32_t)(((wn * 32 + ((lane >> 4) * 8) + (lane & 7)) * BKP +
                    (((lane >> 3) & 1) * 8)) * 2);

    const int frow = tid >> 2;
    const int fkg  = (tid & 3) * 8;
    const int nch = kmax / BK;

#pragma unroll
    for (int i = 0; i < 2; i++) {
        const int row = frow + i * 64;
        const uint32_t so = (uint32_t)(row * BKP + fkg) * 2;
        const size_t ai = (size_t)(m0 + row) * lda + fkg;
        const size_t bi = (size_t)(n0 + row) * ldb + fkg;
        cpasync16(sb + OFF_AHI + so, Ahi + ai);
        cpasync16(sb + OFF_ALO + so, Alo + ai);
        cpasync16(sb + OFF_BHI + so, Bhi + bi);
        cpasync16(sb + OFF_BLO + so, Blo + bi);
    }
    asm volatile("cp.async.commit_group;");

    for (int ch = 0; ch < nch; ch++) {
        const uint32_t base = sb + (uint32_t)(ch & 1) * STAGE;
        if (ch + 1 < nch) {
            const uint32_t nb2 = sb + (uint32_t)((ch + 1) & 1) * STAGE;
            const int k0 = (ch + 1) * BK;
#pragma unroll
            for (int i = 0; i < 2; i++) {
                const int row = frow + i * 64;
                const uint32_t so = (uint32_t)(row * BKP + fkg) * 2;
                const size_t ai = (size_t)(m0 + row) * lda + k0 + fkg;
                const size_t bi = (size_t)(n0 + row) * ldb + k0 + fkg;
                cpasync16(nb2 + OFF_AHI + so, Ahi + ai);
                cpasync16(nb2 + OFF_ALO + so, Alo + ai);
                cpasync16(nb2 + OFF_BHI + so, Bhi + bi);
                cpasync16(nb2 + OFF_BLO + so, Blo + bi);
            }
            asm volatile("cp.async.commit_group;");
            asm volatile("cp.async.wait_group 1;");
        } else {
            asm volatile("cp.async.wait_group 0;");
        }
        __syncthreads();

        const uint32_t aHi = base + OFF_AHI + aoff;
        const uint32_t aLo = base + OFF_ALO + aoff;
        const uint32_t bHi = base + OFF_BHI + boff;
        const uint32_t bLo = base + OFF_BLO + boff;
#pragma unroll
        for (int ks = 0; ks < 2; ks++) {
            uint32_t bh[8], bl[8];
            ldm4(bh + 0, bHi + ks * 32);
            ldm4(bh + 4, bHi + 16 * BKP * 2 + ks * 32);
            ldm4(bl + 0, bLo + ks * 32);
            ldm4(bl + 4, bLo + 16 * BKP * 2 + ks * 32);
#pragma unroll
            for (int mt = 0; mt < 4; mt++) {
                uint32_t ah[4], al[4];
                ldm4(ah, aHi + mt * 16 * BKP * 2 + ks * 32);
                ldm4(al, aLo + mt * 16 * BKP * 2 + ks * 32);
#pragma unroll
                for (int nt = 0; nt < 4; nt++) {
                    mma16816(acc[mt][nt], ah, &bh[nt * 2]);
                    mma16816(acc[mt][nt], al, &bh[nt * 2]);
                    mma16816(acc[mt][nt], ah, &bl[nt * 2]);
                }
            }
        }
        __syncthreads();
    }
}

// ---------------- merged QKV GEMM + fused rmsnorm/rope/split epilogue ----
__global__ void __launch_bounds__(NTHR)
k_mma_qkv(const bf* __restrict__ xh, const bf* __restrict__ xl,
          const bf* __restrict__ Wh, const bf* __restrict__ Wl,
          float* __restrict__ vp,
          bf* __restrict__ qhmh, bf* __restrict__ qhml,
          bf* __restrict__ khmh, bf* __restrict__ khml,
          const float* __restrict__ cosb, const float* __restrict__ sinb,
          const float* __restrict__ qs, const float* __restrict__ ks)
{
    extern __shared__ char dyn[];
    const int m0 = blockIdx.y * BM, n0 = blockIdx.x * BN;
    float acc[4][4][4];
    mma_compute(dyn, xh, xl, DIN, Wh, Wl, DIN, DIN, m0, n0, acc);

    const int lane = threadIdx.x & 31, wid = threadIdx.x >> 5;
    const int wm = wid & 1, wn = wid >> 1;

    if (n0 >= DOUT + DKV) {
        const int coff = n0 - DOUT - DKV;
#pragma unroll
        for (int mt = 0; mt < 4; mt++)
#pragma unroll
            for (int half = 0; half < 2; half++) {
                const int row = m0 + wm * 64 + mt * 16 + (lane >> 2) + half * 8;
#pragma unroll
                for (int nt = 0; nt < 4; nt++) {
                    const int col = coff + wn * 32 + nt * 8 + (lane & 3) * 2;
                    *reinterpret_cast<float2*>(vp + (size_t)row * DKV + col) =
                        make_float2(acc[mt][nt][half * 2 + 0],
                                    acc[mt][nt][half * 2 + 1]);
                }
            }
        return;
    }

    const bool isQ = (n0 < DOUT);
    const float* scale = isQ ? qs : ks;
    bf* oh = isQ ? qhmh : khmh;
    bf* ol = isQ ? qhml : khml;
    const int nheads = isQ ? NH : KVH;
    const int h = (isQ ? n0 : (n0 - DOUT)) / HD;
    const float alpha = isQ ? 0.08838834764831845f : 1.0f;

    float* rsum = reinterpret_cast<float*>(dyn);                 // [128][4]
    float* stg  = reinterpret_cast<float*>(dyn + 2048);          // [128][132]

#pragma unroll
    for (int mt = 0; mt < 4; mt++)
#pragma unroll
        for (int half = 0; half < 2; half++) {
            const int rl = wm * 64 + mt * 16 + (lane >> 2) + half * 8;
            float part = 0.f;
#pragma unroll
            for (int nt = 0; nt < 4; nt++) {
                const float vx = acc[mt][nt][half * 2 + 0];
                const float vy = acc[mt][nt][half * 2 + 1];
                part += vx * vx + vy * vy;
            }
            part += __shfl_xor_sync(0xffffffffu, part, 1);
            part += __shfl_xor_sync(0xffffffffu, part, 2);
            if ((lane & 3) == 0) rsum[rl * 4 + wn] = part;
        }
    __syncthreads();

#pragma unroll
    for (int mt = 0; mt < 4; mt++)
#pragma unroll
        for (int half = 0; half < 2; half++) {
            const int rl = wm * 64 + mt * 16 + (lane >> 2) + half * 8;
            const float tot = rsum[rl * 4 + 0] + rsum[rl * 4 + 1] +
                              rsum[rl * 4 + 2] + rsum[rl * 4 + 3];
            const float rinv = rsqrtf(tot * (1.0f / HD) + 1e-6f) * alpha;
#pragma unroll
            for (int nt = 0; nt < 4; nt++) {
                const int c = wn * 32 + nt * 8 + (lane & 3) * 2;
                stg[rl * 132 + c]     = acc[mt][nt][half * 2 + 0] * rinv * scale[c];
                stg[rl * 132 + c + 1] = acc[mt][nt][half * 2 + 1] * rinv * scale[c + 1];
            }
        }
    __syncthreads();

#pragma unroll
    for (int mt = 0; mt < 4; mt++)
#pragma unroll
        for (int half = 0; half < 2; half++) {
            const int rl = wm * 64 + mt * 16 + (lane >> 2) + half * 8;
            const int row = m0 + rl;
            const int b = row >> 11, pos = row & (SS - 1);
#pragma unroll
            for (int nt = 0; nt < 4; nt++) {
                const int c = wn * 32 + nt * 8 + (lane & 3) * 2;
                const float xn0 = stg[rl * 132 + c];
                const float xn1 = stg[rl * 132 + c + 1];
                const int p = (c + 64) & 127;
                const float s0 = stg[rl * 132 + p];
                const float s1 = stg[rl * 132 + p + 1];
                const float rot0 = (c < 64) ? -s0 : s0;
                const float rot1 = (c < 64) ? -s1 : s1;
                const float o0 = xn0 * cosb[pos * HD + c]     + rot0 * sinb[pos * HD + c];
                const float o1 = xn1 * cosb[pos * HD + c + 1] + rot1 * sinb[pos * HD + c + 1];
                const size_t oi = ((size_t)(b * nheads + h) * SS + pos) * HD + c;
                split2(o0, o1, oh, ol, oi);
            }
        }
}

// ---------------- O-projection: tf32 single-term NT GEMM ----------------
// out[BS, DIN] = ctxf[BS, DOUT] @ WoT[DIN, DOUT]^T (both operands tf32-rounded)
__global__ void __launch_bounds__(NTHR, 2)
k_mma_o(const float* __restrict__ A, const float* __restrict__ B,
        float* __restrict__ C)
{
    extern __shared__ char dyn[];
    float* As = reinterpret_cast<float*>(dyn);
    const uint32_t sb = smem_u32(dyn);
    const int tid  = threadIdx.x;
    const int lane = tid & 31;
    const int wid  = tid >> 5;
    const int wm   = wid & 1;
    const int wn   = wid >> 1;
    const int g    = lane >> 2;        // 0..7
    const int cq   = lane & 3;         // 0..3
    const int m0 = blockIdx.y * BM, n0 = blockIdx.x * BN;

    float acc[4][4][4];
#pragma unroll
    for (int i = 0; i < 4; i++)
#pragma unroll
        for (int j = 0; j < 4; j++)
#pragma unroll
            for (int k = 0; k < 4; k++) acc[i][j][k] = 0.f;

    const int frow = tid >> 3;              // 0..31 (x4 = 128 rows over 4 iters)
    const int fc   = tid & 7;               // 16B chunk within 128B row
    const int nch  = DOUT / BK;             // 64

    auto fill = [&](int ch) {
        const uint32_t st = sb + (uint32_t)(ch & 1) * OSTAGE;
        const int k0 = ch * BK;
#pragma unroll
        for (int it = 0; it < 4; it++) {
            const int row = frow + it * 32;
            const uint32_t so = (uint32_t)(row * (OKP * 4) + fc * 16);
            cpasync16(st + so, A + (size_t)(m0 + row) * DOUT + k0 + fc * 4);
            cpasync16(st + OTILE + so, B + (size_t)(n0 + row) * DOUT + k0 + fc * 4);
        }
        asm volatile("cp.async.commit_group;");
    };

    fill(0);
    for (int ch = 0; ch < nch; ch++) {
        if (ch + 1 < nch) {
            fill(ch + 1);
            asm volatile("cp.async.wait_group 1;");
        } else {
            asm volatile("cp.async.wait_group 0;");
        }
        __syncthreads();

        const int abase = ((ch & 1) * (OSTAGE / 4)) + (wm * 64) * OKP;
        const int bbase = ((ch & 1) * (OSTAGE / 4)) + (OTILE / 4) + (wn * 32) * OKP;
#pragma unroll
        for (int ks = 0; ks < 4; ks++) {
            uint32_t bfr[8];
#pragma unroll
            for (int nt = 0; nt < 4; nt++) {
                const int nb = bbase + (nt * 8 + g) * OKP + ks * 8;
                bfr[nt * 2 + 0] = __float_as_uint(As[nb + cq]);
                bfr[nt * 2 + 1] = __float_as_uint(As[nb + cq + 4]);
            }
#pragma unroll
            for (int mt = 0; mt < 4; mt++) {
                const int ab = abase + (mt * 16 + g) * OKP + ks * 8;
                uint32_t afr[4];
                afr[0] = __float_as_uint(As[ab + cq]);
                afr[1] = __float_as_uint(As[ab + 8 * OKP + cq]);
                afr[2] = __float_as_uint(As[ab + cq + 4]);
                afr[3] = __float_as_uint(As[ab + 8 * OKP + cq + 4]);
#pragma unroll
                for (int nt = 0; nt < 4; nt++)
                    mma1688tf32(acc[mt][nt], afr, &bfr[nt * 2]);
            }
        }
        __syncthreads();
    }

#pragma unroll
    for (int mt = 0; mt < 4; mt++)
#pragma unroll
        for (int half = 0; half < 2; half++) {
            const int row = m0 + wm * 64 + mt * 16 + g + half * 8;
#pragma unroll
            for (int nt = 0; nt < 4; nt++) {
                const int col = n0 + wn * 32 + nt * 8 + cq * 2;
                *reinterpret_cast<float2*>(C + (size_t)row * DIN + col) =
                    make_float2(acc[mt][nt][half * 2 + 0],
                                acc[mt][nt][half * 2 + 1]);
            }
        }
}

// ---------------- fused flash attention (bf16x3 HMMA) ----------------
__global__ void __launch_bounds__(256, 1)
k_attn(const bf* __restrict__ qhp, const bf* __restrict__ qlp,
       const bf* __restrict__ khp, const bf* __restrict__ klp,
       const bf* __restrict__ vhp, const bf* __restrict__ vlp,
       float* __restrict__ ctxf)
{
    extern __shared__ char dyn[];
    const uint32_t sb = smem_u32(dyn);
    const int tid = threadIdx.x, lane = tid & 31, w = tid >> 5;
    const int bh = blockIdx.y, b = bh / NH, h = bh % NH;
    const int kvh = (bh % NH) / GRP;
    const int m0 = ((int)gridDim.x - 1 - (int)blockIdx.x) * FBM;
    const size_t qo = (size_t)bh * SS * HD;
    const size_t ko = (size_t)(b * KVH + kvh) * SS * HD;
    const size_t vo = (size_t)(b * KVH + kvh) * HD * SS;

#pragma unroll
    for (int it = 0; it < 8; it++) {
        const int c = tid + it * 256;
        const int row = c >> 4, col = (c & 15) * 8;
        const size_t gi = qo + (size_t)(m0 + row) * HD + col;
        cpasync16(sb + (uint32_t)(row * QSP + col) * 2, qhp + gi);
        cpasync16(sb + QBYTES + (uint32_t)(row * QSP + col) * 2, qlp + gi);
    }
    asm volatile("cp.async.commit_group;");
    asm volatile("cp.async.wait_group 0;");
    __syncthreads();

    uint32_t qfh[8][4], qfl[8][4];
    {
        const uint32_t ab = sb +
            (uint32_t)(((w * 16 + (lane & 15)) * QSP + (lane >> 4) * 8) * 2);
#pragma unroll
        for (int kk = 0; kk < 8; kk++) {
            ldm4(qfh[kk], ab + kk * 32);
            ldm4(qfl[kk], ab + QBYTES + kk * 32);
        }
    }
    __syncthreads();

    const int nb = m0 / FBN + 2;

    auto load_kv = [&](int i) {
        if (i < nb) {
            const int n0 = i * FBN;
            const uint32_t bufb = sb + (uint32_t)(i & 1) * FSTAGE;
#pragma unroll
            for (int it = 0; it < 4; it++) {
                const int c = tid + it * 256;
                const int krow = c >> 4, kcol = (c & 15) * 8;
                const size_t gk = ko + (size_t)(n0 + krow) * HD + kcol;
                cpasync16(bufb + (uint32_t)(krow * KSP + kcol) * 2, khp + gk);
                cpasync16(bufb + KTILE + (uint32_t)(krow * KSP + kcol) * 2, klp + gk);
                const int vrow = c >> 3, vcol = (c & 7) * 8;
                const size_t gv = vo + (size_t)vrow * SS + n0 + vcol;
                cpasync16(bufb + 2 * KTILE + (uint32_t)(vrow * VSP + vcol) * 2, vhp + gv);
                cpasync16(bufb + 2 * KTILE + VTILE + (uint32_t)(vrow * VSP + vcol) * 2, vlp + gv);
            }
        }
        asm volatile("cp.async.commit_group;");
    };

    load_kv(0);
    load_kv(1);

    float ctxa[16][4];
#pragma unroll
    for (int j = 0; j < 16; j++)
#pragma unroll
        for (int e = 0; e < 4; e++) ctxa[j][e] = 0.f;
    float mrow0 = -1e30f, mrow8 = -1e30f, lrow0 = 0.f, lrow8 = 0.f;

    const uint32_t kboff =
        (uint32_t)((((lane >> 4) * 8 + (lane & 7)) * KSP + ((lane >> 3) & 1) * 8) * 2);
    const uint32_t vboff =
        (uint32_t)((((lane >> 4) * 8 + (lane & 7)) * VSP + ((lane >> 3) & 1) * 8) * 2);
    const int r0g = m0 + w * 16 + (lane >> 2);
    const int cquad = 2 * (lane & 3);

    for (int i = 0; i < nb; i++) {
        asm volatile("cp.async.wait_group 1;");
        __syncthreads();
        const uint32_t base = sb + (uint32_t)(i & 1) * FSTAGE;
        const int n0 = i * FBN;

        float s[8][4];
#pragma unroll
        for (int j = 0; j < 8; j++)
#pragma unroll
            for (int e = 0; e < 4; e++) s[j][e] = 0.f;

        const uint32_t kb = base + kboff;
#pragma unroll
        for (int kk = 0; kk < 8; kk++) {
#pragma unroll
            for (int ng = 0; ng < 4; ng++) {
                uint32_t bh4[4], bl4[4];
                const uint32_t a = kb + (uint32_t)(ng * 16 * KSP * 2) + kk * 32;
                ldm4(bh4, a);
                ldm4(bl4, a + KTILE);
                mma16816(s[2 * ng + 0], qfh[kk], bh4 + 0);
                mma16816(s[2 * ng + 0], qfl[kk], bh4 + 0);
                mma16816(s[2 * ng + 0], qfh[kk], bl4 + 0);
                mma16816(s[2 * ng + 1], qfh[kk], bh4 + 2);
                mma16816(s[2 * ng + 1], qfl[kk], bh4 + 2);
                mma16816(s[2 * ng + 1], qfh[kk], bl4 + 2);
            }
        }

        if (n0 + FBN - 1 > m0) {
#pragma unroll
            for (int j = 0; j < 8; j++) {
                const int col = n0 + j * 8 + cquad;
                if (col > r0g)         s[j][0] = -1e30f;
                if (col + 1 > r0g)     s[j][1] = -1e30f;
                if (col > r0g + 8)     s[j][2] = -1e30f;
                if (col + 1 > r0g + 8) s[j][3] = -1e30f;
            }
        }

        float mx0 = -1e30f, mx8 = -1e30f;
#pragma unroll
        for (int j = 0; j < 8; j++) {
            mx0 = fmaxf(mx0, fmaxf(s[j][0], s[j][1]));
            mx8 = fmaxf(mx8, fmaxf(s[j][2], s[j][3]));
        }
        mx0 = fmaxf(mx0, __shfl_xor_sync(0xffffffffu, mx0, 1));
        mx0 = fmaxf(mx0, __shfl_xor_sync(0xffffffffu, mx0, 2));
        mx8 = fmaxf(mx8, __shfl_xor_sync(0xffffffffu, mx8, 1));
        mx8 = fmaxf(mx8, __shfl_xor_sync(0xffffffffu, mx8, 2));

        const float mn0 = fmaxf(mrow0, mx0), mn8 = fmaxf(mrow8, mx8);
        const float sc0 = __expf(mrow0 - mn0), sc8 = __expf(mrow8 - mn8);
        mrow0 = mn0; mrow8 = mn8;

        float sum0 = 0.f, sum8 = 0.f;
        uint32_t ph[4][4], pl[4][4];
#pragma unroll
        for (int g = 0; g < 4; g++) {
#pragma unroll
            for (int jj = 0; jj < 2; jj++) {
                const int j = 2 * g + jj;
                const float e0 = __expf(s[j][0] - mn0);
                const float e1 = __expf(s[j][1] - mn0);
                const float e2 = __expf(s[j][2] - mn8);
                const float e3 = __expf(s[j][3] - mn8);
                sum0 += e0 + e1; sum8 += e2 + e3;
                bf h0 = __float2bfloat16(e0), h1 = __float2bfloat16(e1);
                bf h2 = __float2bfloat16(e2), h3 = __float2bfloat16(e3);
                ph[g][2 * jj + 0] = pack_bf(h0, h1);
                ph[g][2 * jj + 1] = pack_bf(h2, h3);
                pl[g][2 * jj + 0] = pack_bf(
                    __float2bfloat16(e0 - __bfloat162float(h0)),
                    __float2bfloat16(e1 - __bfloat162float(h1)));
                pl[g][2 * jj + 1] = pack_bf(
                    __float2bfloat16(e2 - __bfloat162float(h2)),
                    __float2bfloat16(e3 - __bfloat162float(h3)));
            }
        }
        sum0 += __shfl_xor_sync(0xffffffffu, sum0, 1);
        sum0 += __shfl_xor_sync(0xffffffffu, sum0, 2);
        sum8 += __shfl_xor_sync(0xffffffffu, sum8, 1);
        sum8 += __shfl_xor_sync(0xffffffffu, sum8, 2);
        lrow0 = lrow0 * sc0 + sum0;
        lrow8 = lrow8 * sc8 + sum8;

#pragma unroll
        for (int j = 0; j < 16; j++) {
            ctxa[j][0] *= sc0; ctxa[j][1] *= sc0;
            ctxa[j][2] *= sc8; ctxa[j][3] *= sc8;
        }

        const uint32_t vb = base + 2 * KTILE + vboff;
#pragma unroll
        for (int g = 0; g < 4; g++) {
#pragma unroll
            for (int ng = 0; ng < 8; ng++) {
                uint32_t vh4[4], vl4[4];
                const uint32_t a = vb + (uint32_t)(ng * 16 * VSP * 2) + g * 32;
                ldm4(vh4, a);
                ldm4(vl4, a + VTILE);
                mma16816(ctxa[2 * ng + 0], ph[g], vh4 + 0);
                mma16816(ctxa[2 * ng + 0], pl[g], vh4 + 0);
                mma16816(ctxa[2 * ng + 0], ph[g], vl4 + 0);
                mma16816(ctxa[2 * ng + 1], ph[g], vh4 + 2);
                mma16816(ctxa[2 * ng + 1], pl[g], vh4 + 2);
                mma16816(ctxa[2 * ng + 1], ph[g], vl4 + 2);
            }
        }
        __syncthreads();
        load_kv(i + 2);
    }

    // epilogue: normalize + tf32-round + fp32 store (O-proj operand)
    const float inv0 = 1.0f / lrow0, inv8 = 1.0f / lrow8;
    const int r0 = m0 + w * 16 + (lane >> 2);
#pragma unroll
    for (int j = 0; j < 16; j++) {
        const int col = h * HD + j * 8 + cquad;
        const size_t i0 = ((size_t)b * SS + r0) * DOUT + col;
        const size_t i8 = ((size_t)b * SS + r0 + 8) * DOUT + col;
        *reinterpret_cast<float2*>(ctxf + i0) =
            make_float2(tf32r(ctxa[j][0] * inv0), tf32r(ctxa[j][1] * inv0));
        *reinterpret_cast<float2*>(ctxf + i8) =
            make_float2(tf32r(ctxa[j][2] * inv8), tf32r(ctxa[j][3] * inv8));
    }
}

// ---------------- prep kernels ----------------
__global__ void k_split(const float* __restrict__ in, bf* __restrict__ hi,
                        bf* __restrict__ lo, int n)
{
    const int i = (blockIdx.x * blockDim.x + threadIdx.x) * 2;
    if (i < n) {
        float2 v = *reinterpret_cast<const float2*>(in + i);
        split2(v.x, v.y, hi, lo, (size_t)i);
    }
}

__global__ void k_tsplit(const float* __restrict__ in, int ldin,
                         bf* __restrict__ oh, bf* __restrict__ ol, int ldout)
{
    __shared__ float t[32][33];
    const int c0 = blockIdx.x * 32, r0 = blockIdx.y * 32;
    const int tx = threadIdx.x, ty = threadIdx.y;
#pragma unroll
    for (int i = 0; i < 32; i += 8)
        t[ty + i][tx] = in[(size_t)(r0 + ty + i) * ldin + c0 + tx];
    __syncthreads();
#pragma unroll
    for (int i = 0; i < 32; i += 8) {
        const float v = t[tx][ty + i];
        const size_t idx = (size_t)(c0 + ty + i) * ldout + r0 + tx;
        bf h = __float2bfloat16(v);
        oh[idx] = h;
        ol[idx] = __float2bfloat16(v - __bfloat162float(h));
    }
}

// transpose + tf32-round (fp32 out) for Wo
__global__ void k_ttf32(const float* __restrict__ in, int ldin,
                        float* __restrict__ outp, int ldout)
{
    __shared__ float t[32][33];
    const int c0 = blockIdx.x * 32, r0 = blockIdx.y * 32;
    const int tx = threadIdx.x, ty = threadIdx.y;
#pragma unroll
    for (int i = 0; i < 32; i += 8)
        t[ty + i][tx] = in[(size_t)(r0 + ty + i) * ldin + c0 + tx];
    __syncthreads();
#pragma unroll
    for (int i = 0; i < 32; i += 8)
        outp[(size_t)(c0 + ty + i) * ldout + r0 + tx] = tf32r(t[tx][ty + i]);
}

__global__ void k_vtrans(const float* __restrict__ vp,
                         bf* __restrict__ oh, bf* __restrict__ ol)
{
    __shared__ float t[32][33];
    const int z = blockIdx.z;
    const int b = z / KVH, kv = z % KVH;
    const float* ip = vp + (size_t)b * SS * DKV + kv * HD;
    const size_t obase = (size_t)z * HD * SS;
    const int c0 = blockIdx.x * 32, r0 = blockIdx.y * 32;
    const int tx = threadIdx.x, ty = threadIdx.y;
#pragma unroll
    for (int i = 0; i < 32; i += 8)
        t[ty + i][tx] = ip[(size_t)(r0 + ty + i) * DKV + c0 + tx];
    __syncthreads();
#pragma unroll
    for (int i = 0; i < 32; i += 8) {
        const float v = t[tx][ty + i];
        const size_t idx = obase + (size_t)(c0 + ty + i) * SS + r0 + tx;
        bf h = __float2bfloat16(v);
        oh[idx] = h;
        ol[idx] = __float2bfloat16(v - __bfloat162float(h));
    }
}

// ---------------- launch ----------------
extern "C" void kernel_launch(void* const* d_in, const int* in_sizes, int n_in,
                              void* d_out, int out_size)
{
    const float* x    = (const float*)d_in[0];
    const float* cosb = (const float*)d_in[2];
    const float* sinb = (const float*)d_in[3];
    const float* Wq   = (const float*)d_in[4];
    const float* Wk   = (const float*)d_in[5];
    const float* Wv   = (const float*)d_in[6];
    const float* Wo   = (const float*)d_in[7];
    const float* qs   = (const float*)d_in[8];
    const float* ks   = (const float*)d_in[9];
    float* out = (float*)d_out;

    float *vp, *ctxf, *WoT;
    bf *xh, *xl, *WTh, *WTl;
    bf *qhmh, *qhml, *khmh, *khml, *vTh, *vTl;
    cudaGetSymbolAddress((void**)&vp,   g_vp);
    cudaGetSymbolAddress((void**)&ctxf, g_ctxf);
    cudaGetSymbolAddress((void**)&WoT,  g_WoT);
    cudaGetSymbolAddress((void**)&xh,   g_xh);
    cudaGetSymbolAddress((void**)&xl,   g_xl);
    cudaGetSymbolAddress((void**)&WTh,  g_WTh);
    cudaGetSymbolAddress((void**)&WTl,  g_WTl);
    cudaGetSymbolAddress((void**)&qhmh, g_qhmh);
    cudaGetSymbolAddress((void**)&qhml, g_qhml);
    cudaGetSymbolAddress((void**)&khmh, g_khmh);
    cudaGetSymbolAddress((void**)&khml, g_khml);
    cudaGetSymbolAddress((void**)&vTh,  g_vTh);
    cudaGetSymbolAddress((void**)&vTl,  g_vTl);

    cudaFuncSetAttribute(k_mma_qkv, cudaFuncAttributeMaxDynamicSharedMemorySize, SMEM_DYN);
    cudaFuncSetAttribute(k_mma_o,   cudaFuncAttributeMaxDynamicSharedMemorySize, OSMEM);
    cudaFuncSetAttribute(k_attn,    cudaFuncAttributeMaxDynamicSharedMemorySize, FSMEM);

    const dim3 tb(32, 8);

    // Prep: transpose+split QKV weights, tf32 transpose for Wo, split x
    k_tsplit<<<dim3(DOUT / 32, DIN / 32), tb>>>(Wq, DOUT, WTh, WTl, DIN);
    k_tsplit<<<dim3(DKV / 32, DIN / 32), tb>>>(Wk, DKV,
        WTh + (size_t)DOUT * DIN, WTl + (size_t)DOUT * DIN, DIN);
    k_tsplit<<<dim3(DKV / 32, DIN / 32), tb>>>(Wv, DKV,
        WTh + (size_t)(DOUT + DKV) * DIN, WTl + (size_t)(DOUT + DKV) * DIN, DIN);
    k_ttf32<<<dim3(DIN / 32, DOUT / 32), tb>>>(Wo, DIN, WoT, DOUT);
    k_split<<<(BS * DIN / 2 + 255) / 256, 256>>>(x, xh, xl, BS * DIN);

    // Merged QKV projection with fused rmsnorm+rope+split epilogue
    k_mma_qkv<<<dim3(NQKV / BN, BS / BM), NTHR, SMEM_DYN>>>(
        xh, xl, WTh, WTl, vp, qhmh, qhml, khmh, khml, cosb, sinb, qs, ks);

    // V transpose + split
    k_vtrans<<<dim3(HD / 32, SS / 32, BB * KVH), tb>>>(vp, vTh, vTl);

    // Fused flash attention (writes tf32-rounded fp32 ctx)
    k_attn<<<dim3(SS / FBM, BB * NH), 256, FSMEM>>>(
        qhmh, qhml, khmh, khml, vTh, vTl, ctxf);

    // Output projection: tf32 single-term
    k_mma_o<<<dim3(DIN / BN, BS / BM), NTHR, OSMEM>>>(ctxf, WoT, out);
}

// round 12
// speedup vs baseline: 1.3389x; 1.1915x over previous
#include <cuda_runtime.h>
#include <cuda_bf16.h>
#include <stdint.h>
#include <math.h>

// ---------------- problem constants ----------------
#define BB   2
#define SS   2048
#define DIN  2048
#define NH   16
#define KVH  4
#define HD   128
#define GRP  (NH / KVH)            // 4
#define DOUT (NH * HD)             // 2048
#define DKV  (KVH * HD)            // 512
#define BS   (BB * SS)             // 4096
#define NQKV (DOUT + 2 * DKV)      // 3072

#define BM 128
#define BN 128
#define NTHR 256

// ---------------- tf32 dense tiling ----------------
#define OKP   36                         // fp32 row stride (floats)
#define OTILE (128 * OKP * 4)            // 18432 B per operand tile
#define OSTAGE (2 * OTILE)               // 36864 B
#define OSMEM (2 * OSTAGE)               // 73728 B -> 2 CTAs/SM
#define OBK   32

// ---------------- fused attention tiling ----------------
#define FBM 128
#define FBN 64
#define KSP 136                           // K bf16 row stride (elems)
#define VSP 72                            // V fp32 row stride (floats)
#define QSP 136
#define KTILE (64 * KSP * 2)              // 17408 B
#define VTILE (128 * VSP * 4)             // 36864 B
#define FSTAGE (2 * KTILE + VTILE)        // 71680 B
#define FSMEM (2 * FSTAGE)                // 143360 B
#define QBYTES (128 * QSP * 2)

typedef __nv_bfloat16 bf;

// ---------------- device scratch ----------------
__device__ float g_vp  [(size_t)BS * DKV];
__device__ float g_ctxf[(size_t)BS * DOUT];          // tf32-rounded fp32
__device__ float g_xt  [(size_t)BS * DIN];           // tf32-rounded x
__device__ float g_WTf [(size_t)NQKV * DIN];         // tf32 q|k|v transposed
__device__ float g_WoT [(size_t)DIN * DOUT];         // tf32 Wo transposed
__device__ float g_vT  [(size_t)BB * KVH * HD * SS]; // tf32 V^T

__device__ bf g_qhmh[(size_t)BS * DOUT],  g_qhml[(size_t)BS * DOUT];
__device__ bf g_khmh[(size_t)BS * DKV],   g_khml[(size_t)BS * DKV];

// ---------------- helpers ----------------
__device__ __forceinline__ uint32_t smem_u32(const void* p) {
    uint32_t a;
    asm("{ .reg .u64 t; cvta.to.shared.u64 t, %1; cvt.u32.u64 %0, t; }"
        : "=r"(a) : "l"(p));
    return a;
}
__device__ __forceinline__ uint32_t pack_bf(bf a, bf b) {
    uint16_t ua = *reinterpret_cast<uint16_t*>(&a);
    uint16_t ub = *reinterpret_cast<uint16_t*>(&b);
    return (uint32_t)ua | ((uint32_t)ub << 16);
}
__device__ __forceinline__ void split2(float x, float y, bf* hi, bf* lo,
                                       size_t idx) {
    bf h0 = __float2bfloat16(x), h1 = __float2bfloat16(y);
    bf l0 = __float2bfloat16(x - __bfloat162float(h0));
    bf l1 = __float2bfloat16(y - __bfloat162float(h1));
    *reinterpret_cast<uint32_t*>(hi + idx) = pack_bf(h0, h1);
    *reinterpret_cast<uint32_t*>(lo + idx) = pack_bf(l0, l1);
}
__device__ __forceinline__ float tf32r(float x) {
    float y;
    asm("cvt.rna.tf32.f32 %0, %1;" : "=f"(y) : "f"(x));
    return y;
}
__device__ __forceinline__ void cpasync16(uint32_t dst, const void* src) {
    asm volatile("cp.async.cg.shared.global [%0], [%1], 16;"
                 :: "r"(dst), "l"(src));
}
__device__ __forceinline__ void ldm4(uint32_t* d, uint32_t addr) {
    asm volatile("ldmatrix.sync.aligned.m8n8.x4.shared.b16 {%0,%1,%2,%3}, [%4];"
                 : "=r"(d[0]), "=r"(d[1]), "=r"(d[2]), "=r"(d[3]) : "r"(addr));
}
__device__ __forceinline__ void mma16816(float* c, const uint32_t* a, const uint32_t* b) {
    asm volatile(
        "mma.sync.aligned.m16n8k16.row.col.f32.bf16.bf16.f32 "
        "{%0,%1,%2,%3}, {%4,%5,%6,%7}, {%8,%9}, {%0,%1,%2,%3};"
        : "+f"(c[0]), "+f"(c[1]), "+f"(c[2]), "+f"(c[3])
        : "r"(a[0]), "r"(a[1]), "r"(a[2]), "r"(a[3]), "r"(b[0]), "r"(b[1]));
}
__device__ __forceinline__ void mma1688tf32(float* c, const uint32_t* a, const uint32_t* b) {
    asm volatile(
        "mma.sync.aligned.m16n8k8.row.col.f32.tf32.tf32.f32 "
        "{%0,%1,%2,%3}, {%4,%5,%6,%7}, {%8,%9}, {%0,%1,%2,%3};"
        : "+f"(c[0]), "+f"(c[1]), "+f"(c[2]), "+f"(c[3])
        : "r"(a[0]), "r"(a[1]), "r"(a[2]), "r"(a[3]), "r"(b[0]), "r"(b[1]));
}
__device__ __forceinline__ void mma1688tf32f(float* c, const float* a,
                                             float b0, float b1) {
    uint32_t br[2] = { __float_as_uint(b0), __float_as_uint(b1) };
    uint32_t ar[4] = { __float_as_uint(a[0]), __float_as_uint(a[1]),
                       __float_as_uint(a[2]), __float_as_uint(a[3]) };
    mma1688tf32(c, ar, br);
}

// ---------------- tf32 single-term NT mainloop (2-stage cp.async) --------
// acc = A[m0:+128, 0:K] @ B[n0:+128, 0:K]^T, both operands tf32-pre-rounded
__device__ __forceinline__ void mma_compute_tf32(
    char* dyn, const float* __restrict__ A, const float* __restrict__ B,
    int ld, int K, int m0, int n0, float acc[4][4][4])
{
    float* As = reinterpret_cast<float*>(dyn);
    const uint32_t sb = smem_u32(dyn);
    const int tid  = threadIdx.x;
    const int lane = tid & 31;
    const int wid  = tid >> 5;
    const int wm   = wid & 1;
    const int wn   = wid >> 1;
    const int g    = lane >> 2;
    const int cq   = lane & 3;

#pragma unroll
    for (int i = 0; i < 4; i++)
#pragma unroll
        for (int j = 0; j < 4; j++)
#pragma unroll
            for (int k = 0; k < 4; k++) acc[i][j][k] = 0.f;

    const int frow = tid >> 3;
    const int fc   = tid & 7;
    const int nch  = K / OBK;

    auto fill = [&](int ch) {
        const uint32_t st = sb + (uint32_t)(ch & 1) * OSTAGE;
        const int k0 = ch * OBK;
#pragma unroll
        for (int it = 0; it < 4; it++) {
            const int row = frow + it * 32;
            const uint32_t so = (uint32_t)(row * (OKP * 4) + fc * 16);
            cpasync16(st + so, A + (size_t)(m0 + row) * ld + k0 + fc * 4);
            cpasync16(st + OTILE + so, B + (size_t)(n0 + row) * ld + k0 + fc * 4);
        }
        asm volatile("cp.async.commit_group;");
    };

    fill(0);
    for (int ch = 0; ch < nch; ch++) {
        if (ch + 1 < nch) {
            fill(ch + 1);
            asm volatile("cp.async.wait_group 1;");
        } else {
            asm volatile("cp.async.wait_group 0;");
        }
        __syncthreads();

        const int abase = ((ch & 1) * (OSTAGE / 4)) + (wm * 64) * OKP;
        const int bbase = ((ch & 1) * (OSTAGE / 4)) + (OTILE / 4) + (wn * 32) * OKP;
#pragma unroll
        for (int ks = 0; ks < 4; ks++) {
            uint32_t bfr[8];
#pragma unroll
            for (int nt = 0; nt < 4; nt++) {
                const int nb = bbase + (nt * 8 + g) * OKP + ks * 8;
                bfr[nt * 2 + 0] = __float_as_uint(As[nb + cq]);
                bfr[nt * 2 + 1] = __float_as_uint(As[nb + cq + 4]);
            }
#pragma unroll
            for (int mt = 0; mt < 4; mt++) {
                const int ab = abase + (mt * 16 + g) * OKP + ks * 8;
                uint32_t afr[4];
                afr[0] = __float_as_uint(As[ab + cq]);
                afr[1] = __float_as_uint(As[ab + 8 * OKP + cq]);
                afr[2] = __float_as_uint(As[ab + cq + 4]);
                afr[3] = __float_as_uint(As[ab + 8 * OKP + cq + 4]);
#pragma unroll
                for (int nt = 0; nt < 4; nt++)
                    mma1688tf32(acc[mt][nt], afr, &bfr[nt * 2]);
            }
        }
        __syncthreads();
    }
}

// ---------------- O-projection ----------------
__global__ void __launch_bounds__(NTHR, 2)
k_mma_o(const float* __restrict__ A, const float* __restrict__ B,
        float* __restrict__ C)
{
    extern __shared__ char dyn[];
    const int m0 = blockIdx.y * BM, n0 = blockIdx.x * BN;
    float acc[4][4][4];
    mma_compute_tf32(dyn, A, B, DOUT, DOUT, m0, n0, acc);

    const int lane = threadIdx.x & 31, wid = threadIdx.x >> 5;
    const int wm = wid & 1, wn = wid >> 1;
    const int g = lane >> 2, cq = lane & 3;
#pragma unroll
    for (int mt = 0; mt < 4; mt++)
#pragma unroll
        for (int half = 0; half < 2; half++) {
            const int row = m0 + wm * 64 + mt * 16 + g + half * 8;
#pragma unroll
            for (int nt = 0; nt < 4; nt++) {
                const int col = n0 + wn * 32 + nt * 8 + cq * 2;
                *reinterpret_cast<float2*>(C + (size_t)row * DIN + col) =
                    make_float2(acc[mt][nt][half * 2 + 0],
                                acc[mt][nt][half * 2 + 1]);
            }
        }
}

// ---------------- merged QKV tf32 GEMM + rmsnorm/rope/split epilogue ----
__global__ void __launch_bounds__(NTHR, 2)
k_mma_qkv(const float* __restrict__ xt, const float* __restrict__ W,
          float* __restrict__ vp,
          bf* __restrict__ qhmh, bf* __restrict__ qhml,
          bf* __restrict__ khmh, bf* __restrict__ khml,
          const float* __restrict__ cosb, const float* __restrict__ sinb,
          const float* __restrict__ qs, const float* __restrict__ ks)
{
    extern __shared__ char dyn[];
    const int m0 = blockIdx.y * BM, n0 = blockIdx.x * BN;
    float acc[4][4][4];
    mma_compute_tf32(dyn, xt, W, DIN, DIN, m0, n0, acc);

    const int lane = threadIdx.x & 31, wid = threadIdx.x >> 5;
    const int wm = wid & 1, wn = wid >> 1;

    if (n0 >= DOUT + DKV) {
        const int coff = n0 - DOUT - DKV;
#pragma unroll
        for (int mt = 0; mt < 4; mt++)
#pragma unroll
            for (int half = 0; half < 2; half++) {
                const int row = m0 + wm * 64 + mt * 16 + (lane >> 2) + half * 8;
#pragma unroll
                for (int nt = 0; nt < 4; nt++) {
                    const int col = coff + wn * 32 + nt * 8 + (lane & 3) * 2;
                    *reinterpret_cast<float2*>(vp + (size_t)row * DKV + col) =
                        make_float2(acc[mt][nt][half * 2 + 0],
                                    acc[mt][nt][half * 2 + 1]);
                }
            }
        return;
    }

    const bool isQ = (n0 < DOUT);
    const float* scale = isQ ? qs : ks;
    bf* oh = isQ ? qhmh : khmh;
    bf* ol = isQ ? qhml : khml;
    const int nheads = isQ ? NH : KVH;
    const int h = (isQ ? n0 : (n0 - DOUT)) / HD;
    const float alpha = isQ ? 0.08838834764831845f : 1.0f;

    float* rsum = reinterpret_cast<float*>(dyn);                 // [128][4]
    float* stg  = reinterpret_cast<float*>(dyn + 2048);          // [128][132]

#pragma unroll
    for (int mt = 0; mt < 4; mt++)
#pragma unroll
        for (int half = 0; half < 2; half++) {
            const int rl = wm * 64 + mt * 16 + (lane >> 2) + half * 8;
            float part = 0.f;
#pragma unroll
            for (int nt = 0; nt < 4; nt++) {
                const float vx = acc[mt][nt][half * 2 + 0];
                const float vy = acc[mt][nt][half * 2 + 1];
                part += vx * vx + vy * vy;
            }
            part += __shfl_xor_sync(0xffffffffu, part, 1);
            part += __shfl_xor_sync(0xffffffffu, part, 2);
            if ((lane & 3) == 0) rsum[rl * 4 + wn] = part;
        }
    __syncthreads();

#pragma unroll
    for (int mt = 0; mt < 4; mt++)
#pragma unroll
        for (int half = 0; half < 2; half++) {
            const int rl = wm * 64 + mt * 16 + (lane >> 2) + half * 8;
            const float tot = rsum[rl * 4 + 0] + rsum[rl * 4 + 1] +
                              rsum[rl * 4 + 2] + rsum[rl * 4 + 3];
            const float rinv = rsqrtf(tot * (1.0f / HD) + 1e-6f) * alpha;
#pragma unroll
            for (int nt = 0; nt < 4; nt++) {
                const int c = wn * 32 + nt * 8 + (lane & 3) * 2;
                stg[rl * 132 + c]     = acc[mt][nt][half * 2 + 0] * rinv * scale[c];
                stg[rl * 132 + c + 1] = acc[mt][nt][half * 2 + 1] * rinv * scale[c + 1];
            }
        }
    __syncthreads();

#pragma unroll
    for (int mt = 0; mt < 4; mt++)
#pragma unroll
        for (int half = 0; half < 2; half++) {
            const int rl = wm * 64 + mt * 16 + (lane >> 2) + half * 8;
            const int row = m0 + rl;
            const int b = row >> 11, pos = row & (SS - 1);
#pragma unroll
            for (int nt = 0; nt < 4; nt++) {
                const int c = wn * 32 + nt * 8 + (lane & 3) * 2;
                const float xn0 = stg[rl * 132 + c];
                const float xn1 = stg[rl * 132 + c + 1];
                const int p = (c + 64) & 127;
                const float s0 = stg[rl * 132 + p];
                const float s1 = stg[rl * 132 + p + 1];
                const float rot0 = (c < 64) ? -s0 : s0;
                const float rot1 = (c < 64) ? -s1 : s1;
                const float o0 = xn0 * cosb[pos * HD + c]     + rot0 * sinb[pos * HD + c];
                const float o1 = xn1 * cosb[pos * HD + c + 1] + rot1 * sinb[pos * HD + c + 1];
                const size_t oi = ((size_t)(b * nheads + h) * SS + pos) * HD + c;
                split2(o0, o1, oh, ol, oi);
            }
        }
}

// ---------------- fused flash attention (QK bf16x3, PV tf32) -------------
__global__ void __launch_bounds__(256, 1)
k_attn(const bf* __restrict__ qhp, const bf* __restrict__ qlp,
       const bf* __restrict__ khp, const bf* __restrict__ klp,
       const float* __restrict__ vtp,
       float* __restrict__ ctxf)
{
    extern __shared__ char dyn[];
    const uint32_t sb = smem_u32(dyn);
    float* Vs = reinterpret_cast<float*>(dyn);
    const int tid = threadIdx.x, lane = tid & 31, w = tid >> 5;
    const int bh = blockIdx.y, b = bh / NH, h = bh % NH;
    const int kvh = (bh % NH) / GRP;
    const int m0 = ((int)gridDim.x - 1 - (int)blockIdx.x) * FBM;
    const size_t qo = (size_t)bh * SS * HD;
    const size_t ko = (size_t)(b * KVH + kvh) * SS * HD;
    const size_t vo = (size_t)(b * KVH + kvh) * HD * SS;

#pragma unroll
    for (int it = 0; it < 8; it++) {
        const int c = tid + it * 256;
        const int row = c >> 4, col = (c & 15) * 8;
        const size_t gi = qo + (size_t)(m0 + row) * HD + col;
        cpasync16(sb + (uint32_t)(row * QSP + col) * 2, qhp + gi);
        cpasync16(sb + QBYTES + (uint32_t)(row * QSP + col) * 2, qlp + gi);
    }
    asm volatile("cp.async.commit_group;");
    asm volatile("cp.async.wait_group 0;");
    __syncthreads();

    uint32_t qfh[8][4], qfl[8][4];
    {
        const uint32_t ab = sb +
            (uint32_t)(((w * 16 + (lane & 15)) * QSP + (lane >> 4) * 8) * 2);
#pragma unroll
        for (int kk = 0; kk < 8; kk++) {
            ldm4(qfh[kk], ab + kk * 32);
            ldm4(qfl[kk], ab + QBYTES + kk * 32);
        }
    }
    __syncthreads();

    const int nb = m0 / FBN + 2;

    auto load_kv = [&](int i) {
        if (i < nb) {
            const int n0 = i * FBN;
            const uint32_t bufb = sb + (uint32_t)(i & 1) * FSTAGE;
#pragma unroll
            for (int it = 0; it < 4; it++) {
                const int c = tid + it * 256;
                const int krow = c >> 4, kcol = (c & 15) * 8;
                const size_t gk = ko + (size_t)(n0 + krow) * HD + kcol;
                cpasync16(bufb + (uint32_t)(krow * KSP + kcol) * 2, khp + gk);
                cpasync16(bufb + KTILE + (uint32_t)(krow * KSP + kcol) * 2, klp + gk);
                // V: 128 rows (hd) x 64 fp32 (keys), 16 chunks/row, 2 per c
                const int vrow = c >> 3, vc8 = (c & 7) * 8;
                const float* gv = vtp + vo + (size_t)vrow * SS + n0 + vc8;
                const uint32_t vso = bufb + 2 * KTILE +
                    (uint32_t)(vrow * VSP + vc8) * 4;
                cpasync16(vso, gv);
                cpasync16(vso + 16, gv + 4);
            }
        }
        asm volatile("cp.async.commit_group;");
    };

    load_kv(0);
    load_kv(1);

    float ctxa[16][4];
#pragma unroll
    for (int j = 0; j < 16; j++)
#pragma unroll
        for (int e = 0; e < 4; e++) ctxa[j][e] = 0.f;
    float mrow0 = -1e30f, mrow8 = -1e30f, lrow0 = 0.f, lrow8 = 0.f;

    const uint32_t kboff =
        (uint32_t)((((lane >> 4) * 8 + (lane & 7)) * KSP + ((lane >> 3) & 1) * 8) * 2);
    const int r0g = m0 + w * 16 + (lane >> 2);
    const int cquad = 2 * (lane & 3);
    const int g = lane >> 2;

    for (int i = 0; i < nb; i++) {
        asm volatile("cp.async.wait_group 1;");
        __syncthreads();
        const uint32_t base = sb + (uint32_t)(i & 1) * FSTAGE;
        const int vwbase = (int)((i & 1) * (FSTAGE / 4)) + (2 * KTILE / 4);
        const int n0 = i * FBN;

        float s[8][4];
#pragma unroll
        for (int j = 0; j < 8; j++)
#pragma unroll
            for (int e = 0; e < 4; e++) s[j][e] = 0.f;

        const uint32_t kb = base + kboff;
#pragma unroll
        for (int kk = 0; kk < 8; kk++) {
#pragma unroll
            for (int ng = 0; ng < 4; ng++) {
                uint32_t bh4[4], bl4[4];
                const uint32_t a = kb + (uint32_t)(ng * 16 * KSP * 2) + kk * 32;
                ldm4(bh4, a);
                ldm4(bl4, a + KTILE);
                mma16816(s[2 * ng + 0], qfh[kk], bh4 + 0);
                mma16816(s[2 * ng + 0], qfl[kk], bh4 + 0);
                mma16816(s[2 * ng + 0], qfh[kk], bl4 + 0);
                mma16816(s[2 * ng + 1], qfh[kk], bh4 + 2);
                mma16816(s[2 * ng + 1], qfl[kk], bh4 + 2);
                mma16816(s[2 * ng + 1], qfh[kk], bl4 + 2);
            }
        }

        if (n0 + FBN - 1 > m0) {
#pragma unroll
            for (int j = 0; j < 8; j++) {
                const int col = n0 + j * 8 + cquad;
                if (col > r0g)         s[j][0] = -1e30f;
                if (col + 1 > r0g)     s[j][1] = -1e30f;
                if (col > r0g + 8)     s[j][2] = -1e30f;
                if (col + 1 > r0g + 8) s[j][3] = -1e30f;
            }
        }

        float mx0 = -1e30f, mx8 = -1e30f;
#pragma unroll
        for (int j = 0; j < 8; j++) {
            mx0 = fmaxf(mx0, fmaxf(s[j][0], s[j][1]));
            mx8 = fmaxf(mx8, fmaxf(s[j][2], s[j][3]));
        }
        mx0 = fmaxf(mx0, __shfl_xor_sync(0xffffffffu, mx0, 1));
        mx0 = fmaxf(mx0, __shfl_xor_sync(0xffffffffu, mx0, 2));
        mx8 = fmaxf(mx8, __shfl_xor_sync(0xffffffffu, mx8, 1));
        mx8 = fmaxf(mx8, __shfl_xor_sync(0xffffffffu, mx8, 2));

        const float mn0 = fmaxf(mrow0, mx0), mn8 = fmaxf(mrow8, mx8);
        const float sc0 = __expf(mrow0 - mn0), sc8 = __expf(mrow8 - mn8);
        mrow0 = mn0; mrow8 = mn8;

        float sum0 = 0.f, sum8 = 0.f;
#pragma unroll
        for (int j = 0; j < 8; j++) {
            const float e0 = __expf(s[j][0] - mn0);
            const float e1 = __expf(s[j][1] - mn0);
            const float e2 = __expf(s[j][2] - mn8);
            const float e3 = __expf(s[j][3] - mn8);
            sum0 += e0 + e1; sum8 += e2 + e3;
            // tf32 A-fragment (V k-index permuted to match):
            // {A[r][kq], A[r+8][kq], A[r][kq+4], A[r+8][kq+4]}
            s[j][0] = tf32r(e0);   // (r,   2q) -> slot kq
            s[j][1] = tf32r(e2);   // (r+8, 2q) -> slot kq
            s[j][2] = tf32r(e1);   // (r,   2q+1) -> slot kq+4
            s[j][3] = tf32r(e3);   // (r+8, 2q+1) -> slot kq+4
        }
        sum0 += __shfl_xor_sync(0xffffffffu, sum0, 1);
        sum0 += __shfl_xor_sync(0xffffffffu, sum0, 2);
        sum8 += __shfl_xor_sync(0xffffffffu, sum8, 1);
        sum8 += __shfl_xor_sync(0xffffffffu, sum8, 2);
        lrow0 = lrow0 * sc0 + sum0;
        lrow8 = lrow8 * sc8 + sum8;

#pragma unroll
        for (int j = 0; j < 16; j++) {
            ctxa[j][0] *= sc0; ctxa[j][1] *= sc0;
            ctxa[j][2] *= sc8; ctxa[j][3] *= sc8;
        }

        // PV tf32: B-frag reads V rows permuted within each k8 group
#pragma unroll
        for (int j = 0; j < 8; j++) {
#pragma unroll
            for (int nt = 0; nt < 16; nt++) {
                const int vw = vwbase + (nt * 8 + g) * VSP + j * 8 + cquad;
                const float2 bv = *reinterpret_cast<const float2*>(Vs + vw);
                mma1688tf32f(ctxa[nt], s[j], bv.x, bv.y);
            }
        }
        __syncthreads();
        load_kv(i + 2);
    }

    // epilogue: normalize + tf32-round + fp32 store (O-proj operand)
    const float inv0 = 1.0f / lrow0, inv8 = 1.0f / lrow8;
    const int r0 = m0 + w * 16 + (lane >> 2);
#pragma unroll
    for (int j = 0; j < 16; j++) {
        const int col = h * HD + j * 8 + cquad;
        const size_t i0 = ((size_t)b * SS + r0) * DOUT + col;
        const size_t i8 = ((size_t)b * SS + r0 + 8) * DOUT + col;
        *reinterpret_cast<float2*>(ctxf + i0) =
            make_float2(tf32r(ctxa[j][0] * inv0), tf32r(ctxa[j][1] * inv0));
        *reinterpret_cast<float2*>(ctxf + i8) =
            make_float2(tf32r(ctxa[j][2] * inv8), tf32r(ctxa[j][3] * inv8));
    }
}

// ---------------- prep kernels ----------------
__global__ void k_xround(const float* __restrict__ in, float* __restrict__ outp,
                         int n)
{
    const int i = (blockIdx.x * blockDim.x + threadIdx.x) * 4;
    if (i < n) {
        float4 v = *reinterpret_cast<const float4*>(in + i);
        v.x = tf32r(v.x); v.y = tf32r(v.y); v.z = tf32r(v.z); v.w = tf32r(v.w);
        *reinterpret_cast<float4*>(outp + i) = v;
    }
}

// transpose + tf32-round (fp32 out)
__global__ void k_ttf32(const float* __restrict__ in, int ldin,
                        float* __restrict__ outp, int ldout)
{
    __shared__ float t[32][33];
    const int c0 = blockIdx.x * 32, r0 = blockIdx.y * 32;
    const int tx = threadIdx.x, ty = threadIdx.y;
#pragma unroll
    for (int i = 0; i < 32; i += 8)
        t[ty + i][tx] = in[(size_t)(r0 + ty + i) * ldin + c0 + tx];
    __syncthreads();
#pragma unroll
    for (int i = 0; i < 32; i += 8)
        outp[(size_t)(c0 + ty + i) * ldout + r0 + tx] = tf32r(t[tx][ty + i]);
}

__global__ void k_vtrans(const float* __restrict__ vp, float* __restrict__ vt)
{
    __shared__ float t[32][33];
    const int z = blockIdx.z;
    const int b = z / KVH, kv = z % KVH;
    const float* ip = vp + (size_t)b * SS * DKV + kv * HD;
    const size_t obase = (size_t)z * HD * SS;
    const int c0 = blockIdx.x * 32, r0 = blockIdx.y * 32;
    const int tx = threadIdx.x, ty = threadIdx.y;
#pragma unroll
    for (int i = 0; i < 32; i += 8)
        t[ty + i][tx] = ip[(size_t)(r0 + ty + i) * DKV + c0 + tx];
    __syncthreads();
#pragma unroll
    for (int i = 0; i < 32; i += 8)
        vt[obase + (size_t)(c0 + ty + i) * SS + r0 + tx] = tf32r(t[tx][ty + i]);
}

// ---------------- launch ----------------
extern "C" void kernel_launch(void* const* d_in, const int* in_sizes, int n_in,
                              void* d_out, int out_size)
{
    const float* x    = (const float*)d_in[0];
    const float* cosb = (const float*)d_in[2];
    const float* sinb = (const float*)d_in[3];
    const float* Wq   = (const float*)d_in[4];
    const float* Wk   = (const float*)d_in[5];
    const float* Wv   = (const float*)d_in[6];
    const float* Wo   = (const float*)d_in[7];
    const float* qs   = (const float*)d_in[8];
    const float* ks   = (const float*)d_in[9];
    float* out = (float*)d_out;

    float *vp, *ctxf, *xt, *WTf, *WoT, *vT;
    bf *qhmh, *qhml, *khmh, *khml;
    cudaGetSymbolAddress((void**)&vp,   g_vp);
    cudaGetSymbolAddress((void**)&ctxf, g_ctxf);
    cudaGetSymbolAddress((void**)&xt,   g_xt);
    cudaGetSymbolAddress((void**)&WTf,  g_WTf);
    cudaGetSymbolAddress((void**)&WoT,  g_WoT);
    cudaGetSymbolAddress((void**)&vT,   g_vT);
    cudaGetSymbolAddress((void**)&qhmh, g_qhmh);
    cudaGetSymbolAddress((void**)&qhml, g_qhml);
    cudaGetSymbolAddress((void**)&khmh, g_khmh);
    cudaGetSymbolAddress((void**)&khml, g_khml);

    cudaFuncSetAttribute(k_mma_qkv, cudaFuncAttributeMaxDynamicSharedMemorySize, OSMEM);
    cudaFuncSetAttribute(k_mma_o,   cudaFuncAttributeMaxDynamicSharedMemorySize, OSMEM);
    cudaFuncSetAttribute(k_attn,    cudaFuncAttributeMaxDynamicSharedMemorySize, FSMEM);

    const dim3 tb(32, 8);

    // Prep: tf32 transposes for all weights, tf32 round of x
    k_ttf32<<<dim3(DOUT / 32, DIN / 32), tb>>>(Wq, DOUT, WTf, DIN);
    k_ttf32<<<dim3(DKV / 32, DIN / 32), tb>>>(Wk, DKV, WTf + (size_t)DOUT * DIN, DIN);
    k_ttf32<<<dim3(DKV / 32, DIN / 32), tb>>>(Wv, DKV,
        WTf + (size_t)(DOUT + DKV) * DIN, DIN);
    k_ttf32<<<dim3(DIN / 32, DOUT / 32), tb>>>(Wo, DIN, WoT, DOUT);
    k_xround<<<(BS * DIN / 4 + 255) / 256, 256>>>(x, xt, BS * DIN);

    // Merged QKV projection (tf32) with fused rmsnorm+rope+split epilogue
    k_mma_qkv<<<dim3(NQKV / BN, BS / BM), NTHR, OSMEM>>>(
        xt, WTf, vp, qhmh, qhml, khmh, khml, cosb, sinb, qs, ks);

    // V transpose (tf32-rounded fp32)
    k_vtrans<<<dim3(HD / 32, SS / 32, BB * KVH), tb>>>(vp, vT);

    // Fused flash attention (QK bf16x3, PV tf32)
    k_attn<<<dim3(SS / FBM, BB * NH), 256, FSMEM>>>(
        qhmh, qhml, khmh, khml, vT, ctxf);

    // Output projection (tf32)
    k_mma_o<<<dim3(DIN / BN, BS / BM), NTHR, OSMEM>>>(ctxf, WoT, out);
}

// round 13
// speedup vs baseline: 1.3625x; 1.0176x over previous
#include <cuda_runtime.h>
#include <cuda_bf16.h>
#include <stdint.h>
#include <math.h>

// ---------------- problem constants ----------------
#define BB   2
#define SS   2048
#define DIN  2048
#define NH   16
#define KVH  4
#define HD   128
#define GRP  (NH / KVH)            // 4
#define DOUT (NH * HD)             // 2048
#define DKV  (KVH * HD)            // 512
#define BS   (BB * SS)             // 4096
#define NQKV (DOUT + 2 * DKV)      // 3072

#define BM 128
#define BN 128
#define NTHR 256

// ---------------- tf32 dense tiling ----------------
#define OKP   36                         // fp32 row stride (floats)
#define OTILE (128 * OKP * 4)            // 18432 B per operand tile
#define OSTAGE (2 * OTILE)               // 36864 B
#define OSMEM (2 * OSTAGE)               // 73728 B -> 2 CTAs/SM
#define OBK   32

// ---------------- fused attention tiling ----------------
#define FBM 128
#define FBN 64
#define KSP 136                           // K bf16 row stride (elems)
#define VSP 72                            // V fp32 row stride (floats)
#define QSP 136
#define KTILE (64 * KSP * 2)              // 17408 B
#define VTILE (128 * VSP * 4)             // 36864 B
#define FSTAGE (2 * KTILE + VTILE)        // 71680 B
#define FSMEM (3 * FSTAGE)                // 215040 B (3-stage, 1 CTA/SM)
#define QBYTES (128 * QSP * 2)

typedef __nv_bfloat16 bf;

// ---------------- device scratch ----------------
__device__ float g_ctxf[(size_t)BS * DOUT];          // tf32-rounded fp32
__device__ float g_xt  [(size_t)BS * DIN];           // tf32-rounded x
__device__ float g_WTf [(size_t)NQKV * DIN];         // tf32 q|k|v transposed
__device__ float g_WoT [(size_t)DIN * DOUT];         // tf32 Wo transposed
__device__ float g_vT  [(size_t)BB * KVH * HD * SS]; // tf32 V^T

__device__ bf g_qhmh[(size_t)BS * DOUT],  g_qhml[(size_t)BS * DOUT];
__device__ bf g_khmh[(size_t)BS * DKV],   g_khml[(size_t)BS * DKV];

// ---------------- helpers ----------------
__device__ __forceinline__ uint32_t smem_u32(const void* p) {
    uint32_t a;
    asm("{ .reg .u64 t; cvta.to.shared.u64 t, %1; cvt.u32.u64 %0, t; }"
        : "=r"(a) : "l"(p));
    return a;
}
__device__ __forceinline__ uint32_t pack_bf(bf a, bf b) {
    uint16_t ua = *reinterpret_cast<uint16_t*>(&a);
    uint16_t ub = *reinterpret_cast<uint16_t*>(&b);
    return (uint32_t)ua | ((uint32_t)ub << 16);
}
__device__ __forceinline__ void split2(float x, float y, bf* hi, bf* lo,
                                       size_t idx) {
    bf h0 = __float2bfloat16(x), h1 = __float2bfloat16(y);
    bf l0 = __float2bfloat16(x - __bfloat162float(h0));
    bf l1 = __float2bfloat16(y - __bfloat162float(h1));
    *reinterpret_cast<uint32_t*>(hi + idx) = pack_bf(h0, h1);
    *reinterpret_cast<uint32_t*>(lo + idx) = pack_bf(l0, l1);
}
__device__ __forceinline__ float tf32r(float x) {
    float y;
    asm("cvt.rna.tf32.f32 %0, %1;" : "=f"(y) : "f"(x));
    return y;
}
__device__ __forceinline__ void cpasync16(uint32_t dst, const void* src) {
    asm volatile("cp.async.cg.shared.global [%0], [%1], 16;"
                 :: "r"(dst), "l"(src));
}
__device__ __forceinline__ void ldm4(uint32_t* d, uint32_t addr) {
    asm volatile("ldmatrix.sync.aligned.m8n8.x4.shared.b16 {%0,%1,%2,%3}, [%4];"
                 : "=r"(d[0]), "=r"(d[1]), "=r"(d[2]), "=r"(d[3]) : "r"(addr));
}
__device__ __forceinline__ void mma16816(float* c, const uint32_t* a, const uint32_t* b) {
    asm volatile(
        "mma.sync.aligned.m16n8k16.row.col.f32.bf16.bf16.f32 "
        "{%0,%1,%2,%3}, {%4,%5,%6,%7}, {%8,%9}, {%0,%1,%2,%3};"
        : "+f"(c[0]), "+f"(c[1]), "+f"(c[2]), "+f"(c[3])
        : "r"(a[0]), "r"(a[1]), "r"(a[2]), "r"(a[3]), "r"(b[0]), "r"(b[1]));
}
__device__ __forceinline__ void mma1688tf32(float* c, const uint32_t* a, const uint32_t* b) {
    asm volatile(
        "mma.sync.aligned.m16n8k8.row.col.f32.tf32.tf32.f32 "
        "{%0,%1,%2,%3}, {%4,%5,%6,%7}, {%8,%9}, {%0,%1,%2,%3};"
        : "+f"(c[0]), "+f"(c[1]), "+f"(c[2]), "+f"(c[3])
        : "r"(a[0]), "r"(a[1]), "r"(a[2]), "r"(a[3]), "r"(b[0]), "r"(b[1]));
}
__device__ __forceinline__ void mma1688tf32f(float* c, const float* a,
                                             float b0, float b1) {
    uint32_t br[2] = { __float_as_uint(b0), __float_as_uint(b1) };
    uint32_t ar[4] = { __float_as_uint(a[0]), __float_as_uint(a[1]),
                       __float_as_uint(a[2]), __float_as_uint(a[3]) };
    mma1688tf32(c, ar, br);
}

// ---------------- tf32 single-term NT mainloop (2-stage cp.async) --------
__device__ __forceinline__ void mma_compute_tf32(
    char* dyn, const float* __restrict__ A, const float* __restrict__ B,
    int ld, int K, int m0, int n0, float acc[4][4][4])
{
    float* As = reinterpret_cast<float*>(dyn);
    const uint32_t sb = smem_u32(dyn);
    const int tid  = threadIdx.x;
    const int lane = tid & 31;
    const int wid  = tid >> 5;
    const int wm   = wid & 1;
    const int wn   = wid >> 1;
    const int g    = lane >> 2;
    const int cq   = lane & 3;

#pragma unroll
    for (int i = 0; i < 4; i++)
#pragma unroll
        for (int j = 0; j < 4; j++)
#pragma unroll
            for (int k = 0; k < 4; k++) acc[i][j][k] = 0.f;

    const int frow = tid >> 3;
    const int fc   = tid & 7;
    const int nch  = K / OBK;

    auto fill = [&](int ch) {
        const uint32_t st = sb + (uint32_t)(ch & 1) * OSTAGE;
        const int k0 = ch * OBK;
#pragma unroll
        for (int it = 0; it < 4; it++) {
            const int row = frow + it * 32;
            const uint32_t so = (uint32_t)(row * (OKP * 4) + fc * 16);
            cpasync16(st + so, A + (size_t)(m0 + row) * ld + k0 + fc * 4);
            cpasync16(st + OTILE + so, B + (size_t)(n0 + row) * ld + k0 + fc * 4);
        }
        asm volatile("cp.async.commit_group;");
    };

    fill(0);
    for (int ch = 0; ch < nch; ch++) {
        if (ch + 1 < nch) {
            fill(ch + 1);
            asm volatile("cp.async.wait_group 1;");
        } else {
            asm volatile("cp.async.wait_group 0;");
        }
        __syncthreads();

        const int abase = ((ch & 1) * (OSTAGE / 4)) + (wm * 64) * OKP;
        const int bbase = ((ch & 1) * (OSTAGE / 4)) + (OTILE / 4) + (wn * 32) * OKP;
#pragma unroll
        for (int ks = 0; ks < 4; ks++) {
            uint32_t bfr[8];
#pragma unroll
            for (int nt = 0; nt < 4; nt++) {
                const int nb = bbase + (nt * 8 + g) * OKP + ks * 8;
                bfr[nt * 2 + 0] = __float_as_uint(As[nb + cq]);
                bfr[nt * 2 + 1] = __float_as_uint(As[nb + cq + 4]);
            }
#pragma unroll
            for (int mt = 0; mt < 4; mt++) {
                const int ab = abase + (mt * 16 + g) * OKP + ks * 8;
                uint32_t afr[4];
                afr[0] = __float_as_uint(As[ab + cq]);
                afr[1] = __float_as_uint(As[ab + 8 * OKP + cq]);
                afr[2] = __float_as_uint(As[ab + cq + 4]);
                afr[3] = __float_as_uint(As[ab + 8 * OKP + cq + 4]);
#pragma unroll
                for (int nt = 0; nt < 4; nt++)
                    mma1688tf32(acc[mt][nt], afr, &bfr[nt * 2]);
            }
        }
        __syncthreads();
    }
}

// ---------------- O-projection ----------------
__global__ void __launch_bounds__(NTHR, 2)
k_mma_o(const float* __restrict__ A, const float* __restrict__ B,
        float* __restrict__ C)
{
    extern __shared__ char dyn[];
    const int m0 = blockIdx.y * BM, n0 = blockIdx.x * BN;
    float acc[4][4][4];
    mma_compute_tf32(dyn, A, B, DOUT, DOUT, m0, n0, acc);

    const int lane = threadIdx.x & 31, wid = threadIdx.x >> 5;
    const int wm = wid & 1, wn = wid >> 1;
    const int g = lane >> 2, cq = lane & 3;
#pragma unroll
    for (int mt = 0; mt < 4; mt++)
#pragma unroll
        for (int half = 0; half < 2; half++) {
            const int row = m0 + wm * 64 + mt * 16 + g + half * 8;
#pragma unroll
            for (int nt = 0; nt < 4; nt++) {
                const int col = n0 + wn * 32 + nt * 8 + cq * 2;
                *reinterpret_cast<float2*>(C + (size_t)row * DIN + col) =
                    make_float2(acc[mt][nt][half * 2 + 0],
                                acc[mt][nt][half * 2 + 1]);
            }
        }
}

// ---------------- merged QKV tf32 GEMM + fused epilogues ----------------
__global__ void __launch_bounds__(NTHR, 2)
k_mma_qkv(const float* __restrict__ xt, const float* __restrict__ W,
          float* __restrict__ vT,
          bf* __restrict__ qhmh, bf* __restrict__ qhml,
          bf* __restrict__ khmh, bf* __restrict__ khml,
          const float* __restrict__ cosb, const float* __restrict__ sinb,
          const float* __restrict__ qs, const float* __restrict__ ks)
{
    extern __shared__ char dyn[];
    const int m0 = blockIdx.y * BM, n0 = blockIdx.x * BN;
    float acc[4][4][4];
    mma_compute_tf32(dyn, xt, W, DIN, DIN, m0, n0, acc);

    const int lane = threadIdx.x & 31, wid = threadIdx.x >> 5;
    const int wm = wid & 1, wn = wid >> 1;

    if (n0 >= DOUT + DKV) {
        // ---- V tile: transpose in smem -> vT[kv][hd][tok], tf32-rounded ----
        const int kv = (n0 - DOUT - DKV) / HD;     // tile spans one full kv head
        float* stg = reinterpret_cast<float*>(dyn);  // [128 tok][133]
#pragma unroll
        for (int mt = 0; mt < 4; mt++)
#pragma unroll
            for (int half = 0; half < 2; half++) {
                const int rl = wm * 64 + mt * 16 + (lane >> 2) + half * 8;
#pragma unroll
                for (int nt = 0; nt < 4; nt++) {
                    const int c = wn * 32 + nt * 8 + (lane & 3) * 2;
                    stg[rl * 133 + c]     = tf32r(acc[mt][nt][half * 2 + 0]);
                    stg[rl * 133 + c + 1] = tf32r(acc[mt][nt][half * 2 + 1]);
                }
            }
        __syncthreads();
        const int b = m0 >> 11, pos0 = m0 & (SS - 1);
        float* dst = vT + (size_t)(b * KVH + kv) * HD * SS + pos0;
#pragma unroll
        for (int rr = 0; rr < 16; rr++) {
            const int r = wid * 16 + rr;            // hd row
            float4 v;
            v.x = stg[(lane * 4 + 0) * 133 + r];
            v.y = stg[(lane * 4 + 1) * 133 + r];
            v.z = stg[(lane * 4 + 2) * 133 + r];
            v.w = stg[(lane * 4 + 3) * 133 + r];
            *reinterpret_cast<float4*>(dst + (size_t)r * SS + lane * 4) = v;
        }
        return;
    }

    // ---- Q/K tile: rmsnorm + rope + split, head-major output ----
    const bool isQ = (n0 < DOUT);
    const float* scale = isQ ? qs : ks;
    bf* oh = isQ ? qhmh : khmh;
    bf* ol = isQ ? qhml : khml;
    const int nheads = isQ ? NH : KVH;
    const int h = (isQ ? n0 : (n0 - DOUT)) / HD;
    const float alpha = isQ ? 0.08838834764831845f : 1.0f;

    float* rsum = reinterpret_cast<float*>(dyn);                 // [128][4]
    float* stg  = reinterpret_cast<float*>(dyn + 2048);          // [128][132]

#pragma unroll
    for (int mt = 0; mt < 4; mt++)
#pragma unroll
        for (int half = 0; half < 2; half++) {
            const int rl = wm * 64 + mt * 16 + (lane >> 2) + half * 8;
            float part = 0.f;
#pragma unroll
            for (int nt = 0; nt < 4; nt++) {
                const float vx = acc[mt][nt][half * 2 + 0];
                const float vy = acc[mt][nt][half * 2 + 1];
                part += vx * vx + vy * vy;
            }
            part += __shfl_xor_sync(0xffffffffu, part, 1);
            part += __shfl_xor_sync(0xffffffffu, part, 2);
            if ((lane & 3) == 0) rsum[rl * 4 + wn] = part;
        }
    __syncthreads();

#pragma unroll
    for (int mt = 0; mt < 4; mt++)
#pragma unroll
        for (int half = 0; half < 2; half++) {
            const int rl = wm * 64 + mt * 16 + (lane >> 2) + half * 8;
            const float tot = rsum[rl * 4 + 0] + rsum[rl * 4 + 1] +
                              rsum[rl * 4 + 2] + rsum[rl * 4 + 3];
            const float rinv = rsqrtf(tot * (1.0f / HD) + 1e-6f) * alpha;
#pragma unroll
            for (int nt = 0; nt < 4; nt++) {
                const int c = wn * 32 + nt * 8 + (lane & 3) * 2;
                stg[rl * 132 + c]     = acc[mt][nt][half * 2 + 0] * rinv * scale[c];
                stg[rl * 132 + c + 1] = acc[mt][nt][half * 2 + 1] * rinv * scale[c + 1];
            }
        }
    __syncthreads();

#pragma unroll
    for (int mt = 0; mt < 4; mt++)
#pragma unroll
        for (int half = 0; half < 2; half++) {
            const int rl = wm * 64 + mt * 16 + (lane >> 2) + half * 8;
            const int row = m0 + rl;
            const int b = row >> 11, pos = row & (SS - 1);
#pragma unroll
            for (int nt = 0; nt < 4; nt++) {
                const int c = wn * 32 + nt * 8 + (lane & 3) * 2;
                const float xn0 = stg[rl * 132 + c];
                const float xn1 = stg[rl * 132 + c + 1];
                const int p = (c + 64) & 127;
                const float s0 = stg[rl * 132 + p];
                const float s1 = stg[rl * 132 + p + 1];
                const float rot0 = (c < 64) ? -s0 : s0;
                const float rot1 = (c < 64) ? -s1 : s1;
                const float o0 = xn0 * cosb[pos * HD + c]     + rot0 * sinb[pos * HD + c];
                const float o1 = xn1 * cosb[pos * HD + c + 1] + rot1 * sinb[pos * HD + c + 1];
                const size_t oi = ((size_t)(b * nheads + h) * SS + pos) * HD + c;
                split2(o0, o1, oh, ol, oi);
            }
        }
}

// ---------------- fused flash attention (QK bf16x3, PV tf32) -------------
// 3-stage KV pipeline, one __syncthreads per iteration.
__global__ void __launch_bounds__(256, 1)
k_attn(const bf* __restrict__ qhp, const bf* __restrict__ qlp,
       const bf* __restrict__ khp, const bf* __restrict__ klp,
       const float* __restrict__ vtp,
       float* __restrict__ ctxf)
{
    extern __shared__ char dyn[];
    const uint32_t sb = smem_u32(dyn);
    float* Vs = reinterpret_cast<float*>(dyn);
    const int tid = threadIdx.x, lane = tid & 31, w = tid >> 5;
    const int bh = blockIdx.y, b = bh / NH, h = bh % NH;
    const int kvh = (bh % NH) / GRP;
    const int m0 = ((int)gridDim.x - 1 - (int)blockIdx.x) * FBM;
    const size_t qo = (size_t)bh * SS * HD;
    const size_t ko = (size_t)(b * KVH + kvh) * SS * HD;
    const size_t vo = (size_t)(b * KVH + kvh) * HD * SS;

#pragma unroll
    for (int it = 0; it < 8; it++) {
        const int c = tid + it * 256;
        const int row = c >> 4, col = (c & 15) * 8;
        const size_t gi = qo + (size_t)(m0 + row) * HD + col;
        cpasync16(sb + (uint32_t)(row * QSP + col) * 2, qhp + gi);
        cpasync16(sb + QBYTES + (uint32_t)(row * QSP + col) * 2, qlp + gi);
    }
    asm volatile("cp.async.commit_group;");
    asm volatile("cp.async.wait_group 0;");
    __syncthreads();

    uint32_t qfh[8][4], qfl[8][4];
    {
        const uint32_t ab = sb +
            (uint32_t)(((w * 16 + (lane & 15)) * QSP + (lane >> 4) * 8) * 2);
#pragma unroll
        for (int kk = 0; kk < 8; kk++) {
            ldm4(qfh[kk], ab + kk * 32);
            ldm4(qfl[kk], ab + QBYTES + kk * 32);
        }
    }
    __syncthreads();

    const int nb = m0 / FBN + 2;

    auto load_kv = [&](int i) {
        if (i < nb) {
            const int n0 = i * FBN;
            const uint32_t bufb = sb + (uint32_t)(i % 3) * FSTAGE;
#pragma unroll
            for (int it = 0; it < 4; it++) {
                const int c = tid + it * 256;
                const int krow = c >> 4, kcol = (c & 15) * 8;
                const size_t gk = ko + (size_t)(n0 + krow) * HD + kcol;
                cpasync16(bufb + (uint32_t)(krow * KSP + kcol) * 2, khp + gk);
                cpasync16(bufb + KTILE + (uint32_t)(krow * KSP + kcol) * 2, klp + gk);
                const int vrow = c >> 3, vc8 = (c & 7) * 8;
                const float* gv = vtp + vo + (size_t)vrow * SS + n0 + vc8;
                const uint32_t vso = bufb + 2 * KTILE +
                    (uint32_t)(vrow * VSP + vc8) * 4;
                cpasync16(vso, gv);
                cpasync16(vso + 16, gv + 4);
            }
        }
        asm volatile("cp.async.commit_group;");
    };

    load_kv(0);
    load_kv(1);

    float ctxa[16][4];
#pragma unroll
    for (int j = 0; j < 16; j++)
#pragma unroll
        for (int e = 0; e < 4; e++) ctxa[j][e] = 0.f;
    float mrow0 = -1e30f, mrow8 = -1e30f, lrow0 = 0.f, lrow8 = 0.f;

    const uint32_t kboff =
        (uint32_t)((((lane >> 4) * 8 + (lane & 7)) * KSP + ((lane >> 3) & 1) * 8) * 2);
    const int r0g = m0 + w * 16 + (lane >> 2);
    const int cquad = 2 * (lane & 3);
    const int g = lane >> 2;

    for (int i = 0; i < nb; i++) {
        asm volatile("cp.async.wait_group 1;");
        __syncthreads();
        load_kv(i + 2);                       // prefetch overlaps compute
        const uint32_t base = sb + (uint32_t)(i % 3) * FSTAGE;
        const int vwbase = (int)((i % 3) * (FSTAGE / 4)) + (2 * KTILE / 4);
        const int n0 = i * FBN;

        float s[8][4];
#pragma unroll
        for (int j = 0; j < 8; j++)
#pragma unroll
            for (int e = 0; e < 4; e++) s[j][e] = 0.f;

        const uint32_t kb = base + kboff;
#pragma unroll
        for (int kk = 0; kk < 8; kk++) {
#pragma unroll
            for (int ng = 0; ng < 4; ng++) {
                uint32_t bh4[4], bl4[4];
                const uint32_t a = kb + (uint32_t)(ng * 16 * KSP * 2) + kk * 32;
                ldm4(bh4, a);
                ldm4(bl4, a + KTILE);
                mma16816(s[2 * ng + 0], qfh[kk], bh4 + 0);
                mma16816(s[2 * ng + 0], qfl[kk], bh4 + 0);
                mma16816(s[2 * ng + 0], qfh[kk], bl4 + 0);
                mma16816(s[2 * ng + 1], qfh[kk], bh4 + 2);
                mma16816(s[2 * ng + 1], qfl[kk], bh4 + 2);
                mma16816(s[2 * ng + 1], qfh[kk], bl4 + 2);
            }
        }

        if (n0 + FBN - 1 > m0) {
#pragma unroll
            for (int j = 0; j < 8; j++) {
                const int col = n0 + j * 8 + cquad;
                if (col > r0g)         s[j][0] = -1e30f;
                if (col + 1 > r0g)     s[j][1] = -1e30f;
                if (col > r0g + 8)     s[j][2] = -1e30f;
                if (col + 1 > r0g + 8) s[j][3] = -1e30f;
            }
        }

        float mx0 = -1e30f, mx8 = -1e30f;
#pragma unroll
        for (int j = 0; j < 8; j++) {
            mx0 = fmaxf(mx0, fmaxf(s[j][0], s[j][1]));
            mx8 = fmaxf(mx8, fmaxf(s[j][2], s[j][3]));
        }
        mx0 = fmaxf(mx0, __shfl_xor_sync(0xffffffffu, mx0, 1));
        mx0 = fmaxf(mx0, __shfl_xor_sync(0xffffffffu, mx0, 2));
        mx8 = fmaxf(mx8, __shfl_xor_sync(0xffffffffu, mx8, 1));
        mx8 = fmaxf(mx8, __shfl_xor_sync(0xffffffffu, mx8, 2));

        const float mn0 = fmaxf(mrow0, mx0), mn8 = fmaxf(mrow8, mx8);
        const float sc0 = __expf(mrow0 - mn0), sc8 = __expf(mrow8 - mn8);
        mrow0 = mn0; mrow8 = mn8;

        float sum0 = 0.f, sum8 = 0.f;
#pragma unroll
        for (int j = 0; j < 8; j++) {
            const float e0 = __expf(s[j][0] - mn0);
            const float e1 = __expf(s[j][1] - mn0);
            const float e2 = __expf(s[j][2] - mn8);
            const float e3 = __expf(s[j][3] - mn8);
            sum0 += e0 + e1; sum8 += e2 + e3;
            // tf32 A-fragment (V k-index permuted to match)
            s[j][0] = tf32r(e0);
            s[j][1] = tf32r(e2);
            s[j][2] = tf32r(e1);
            s[j][3] = tf32r(e3);
        }
        sum0 += __shfl_xor_sync(0xffffffffu, sum0, 1);
        sum0 += __shfl_xor_sync(0xffffffffu, sum0, 2);
        sum8 += __shfl_xor_sync(0xffffffffu, sum8, 1);
        sum8 += __shfl_xor_sync(0xffffffffu, sum8, 2);
        lrow0 = lrow0 * sc0 + sum0;
        lrow8 = lrow8 * sc8 + sum8;

#pragma unroll
        for (int j = 0; j < 16; j++) {
            ctxa[j][0] *= sc0; ctxa[j][1] *= sc0;
            ctxa[j][2] *= sc8; ctxa[j][3] *= sc8;
        }

#pragma unroll
        for (int j = 0; j < 8; j++) {
#pragma unroll
            for (int nt = 0; nt < 16; nt++) {
                const int vw = vwbase + (nt * 8 + g) * VSP + j * 8 + cquad;
                const float2 bv = *reinterpret_cast<const float2*>(Vs + vw);
                mma1688tf32f(ctxa[nt], s[j], bv.x, bv.y);
            }
        }
    }

    const float inv0 = 1.0f / lrow0, inv8 = 1.0f / lrow8;
    const int r0 = m0 + w * 16 + (lane >> 2);
#pragma unroll
    for (int j = 0; j < 16; j++) {
        const int col = h * HD + j * 8 + cquad;
        const size_t i0 = ((size_t)b * SS + r0) * DOUT + col;
        const size_t i8 = ((size_t)b * SS + r0 + 8) * DOUT + col;
        *reinterpret_cast<float2*>(ctxf + i0) =
            make_float2(tf32r(ctxa[j][0] * inv0), tf32r(ctxa[j][1] * inv0));
        *reinterpret_cast<float2*>(ctxf + i8) =
            make_float2(tf32r(ctxa[j][2] * inv8), tf32r(ctxa[j][3] * inv8));
    }
}

// ---------------- prep kernels ----------------
__global__ void k_xround(const float* __restrict__ in, float* __restrict__ outp,
                         int n)
{
    const int i = (blockIdx.x * blockDim.x + threadIdx.x) * 4;
    if (i < n) {
        float4 v = *reinterpret_cast<const float4*>(in + i);
        v.x = tf32r(v.x); v.y = tf32r(v.y); v.z = tf32r(v.z); v.w = tf32r(v.w);
        *reinterpret_cast<float4*>(outp + i) = v;
    }
}

// merged weight transposes: flat grid over 4 jobs (Wq, Wk, Wv, Wo)
__global__ void k_wprep(const float* __restrict__ Wq, const float* __restrict__ Wk,
                        const float* __restrict__ Wv, const float* __restrict__ Wo,
                        float* __restrict__ WTf, float* __restrict__ WoT)
{
    __shared__ float t[32][33];
    int bid = blockIdx.x;
    const float* src; float* dst; int ldin, ldout, nbx;
    if (bid < 4096)      { src = Wq; dst = WTf; ldin = DOUT; ldout = DIN; nbx = 64; }
    else if (bid < 5120) { bid -= 4096; src = Wk; dst = WTf + (size_t)DOUT * DIN;
                           ldin = DKV; ldout = DIN; nbx = 16; }
    else if (bid < 6144) { bid -= 5120; src = Wv; dst = WTf + (size_t)(DOUT + DKV) * DIN;
                           ldin = DKV; ldout = DIN; nbx = 16; }
    else                 { bid -= 6144; src = Wo; dst = WoT; ldin = DIN; ldout = DOUT; nbx = 64; }
    const int c0 = (bid % nbx) * 32, r0 = (bid / nbx) * 32;
    const int tx = threadIdx.x, ty = threadIdx.y;
#pragma unroll
    for (int i = 0; i < 32; i += 8)
        t[ty + i][tx] = src[(size_t)(r0 + ty + i) * ldin + c0 + tx];
    __syncthreads();
#pragma unroll
    for (int i = 0; i < 32; i += 8)
        dst[(size_t)(c0 + ty + i) * ldout + r0 + tx] = tf32r(t[tx][ty + i]);
}

// ---------------- launch ----------------
extern "C" void kernel_launch(void* const* d_in, const int* in_sizes, int n_in,
                              void* d_out, int out_size)
{
    const float* x    = (const float*)d_in[0];
    const float* cosb = (const float*)d_in[2];
    const float* sinb = (const float*)d_in[3];
    const float* Wq   = (const float*)d_in[4];
    const float* Wk   = (const float*)d_in[5];
    const float* Wv   = (const float*)d_in[6];
    const float* Wo   = (const float*)d_in[7];
    const float* qs   = (const float*)d_in[8];
    const float* ks   = (const float*)d_in[9];
    float* out = (float*)d_out;

    float *ctxf, *xt, *WTf, *WoT, *vT;
    bf *qhmh, *qhml, *khmh, *khml;
    cudaGetSymbolAddress((void**)&ctxf, g_ctxf);
    cudaGetSymbolAddress((void**)&xt,   g_xt);
    cudaGetSymbolAddress((void**)&WTf,  g_WTf);
    cudaGetSymbolAddress((void**)&WoT,  g_WoT);
    cudaGetSymbolAddress((void**)&vT,   g_vT);
    cudaGetSymbolAddress((void**)&qhmh, g_qhmh);
    cudaGetSymbolAddress((void**)&qhml, g_qhml);
    cudaGetSymbolAddress((void**)&khmh, g_khmh);
    cudaGetSymbolAddress((void**)&khml, g_khml);

    cudaFuncSetAttribute(k_mma_qkv, cudaFuncAttributeMaxDynamicSharedMemorySize, OSMEM);
    cudaFuncSetAttribute(k_mma_o,   cudaFuncAttributeMaxDynamicSharedMemorySize, OSMEM);
    cudaFuncSetAttribute(k_attn,    cudaFuncAttributeMaxDynamicSharedMemorySize, FSMEM);

    // Prep: merged tf32 weight transposes + tf32 round of x
    k_wprep<<<10240, dim3(32, 8)>>>(Wq, Wk, Wv, Wo, WTf, WoT);
    k_xround<<<(BS * DIN / 4 + 255) / 256, 256>>>(x, xt, BS * DIN);

    // Merged QKV projection (tf32): Q/K -> normrope+split, V -> vT direct
    k_mma_qkv<<<dim3(NQKV / BN, BS / BM), NTHR, OSMEM>>>(
        xt, WTf, vT, qhmh, qhml, khmh, khml, cosb, sinb, qs, ks);

    // Fused flash attention (QK bf16x3, PV tf32; 3-stage pipeline)
    k_attn<<<dim3(SS / FBM, BB * NH), 256, FSMEM>>>(
        qhmh, qhml, khmh, khml, vT, ctxf);

    // Output projection (tf32)
    k_mma_o<<<dim3(DIN / BN, BS / BM), NTHR, OSMEM>>>(ctxf, WoT, out);
}

// round 14
// speedup vs baseline: 1.9193x; 1.4086x over previous
#include <cuda_runtime.h>
#include <cuda_fp16.h>
#include <stdint.h>
#include <math.h>

// ---------------- problem constants ----------------
#define BB   2
#define SS   2048
#define DIN  2048
#define NH   16
#define KVH  4
#define HD   128
#define GRP  (NH / KVH)            // 4
#define DOUT (NH * HD)             // 2048
#define DKV  (KVH * HD)            // 512
#define BS   (BB * SS)             // 4096
#define NQKV (DOUT + 2 * DKV)      // 3072

#define BM 128
#define BN 128
#define NTHR 256

// ---------------- fp16-single dense tiling ----------------
#define DKP 40                           // half row stride
#define DTILE (128 * DKP * 2)            // 10240 B per operand tile
#define DSTAGE (2 * DTILE)               // 20480 B
#define DSMEM (2 * DSTAGE)               // 40960 B
#define QKV_SMEM 69632                   // epilogue staging needs more
#define DBK 32

// ---------------- fused attention tiling ----------------
#define FBM 128
#define FBN 64
#define KSP 136                           // K half row stride (elems)
#define VSPH 72                           // V half row stride (elems)
#define QSP 136
#define KTILE (64 * KSP * 2)              // 17408 B (one of hi/lo)
#define VTILEH (128 * VSPH * 2)           // 18432 B
#define FSTAGE (2 * KTILE + VTILEH)       // 53248 B
#define FSMEM (3 * FSTAGE)                // 159744 B (3-stage)
#define QBYTES (128 * QSP * 2)

typedef __half hf;

// ---------------- device scratch ----------------
__device__ hf g_xh  [(size_t)BS * DIN];
__device__ hf g_WTh [(size_t)NQKV * DIN];            // q|k|v transposed fp16
__device__ hf g_WoTh[(size_t)DIN * DOUT];
__device__ hf g_qhmh[(size_t)BS * DOUT], g_qhml[(size_t)BS * DOUT];
__device__ hf g_khmh[(size_t)BS * DKV],  g_khml[(size_t)BS * DKV];
__device__ hf g_vTh [(size_t)BB * KVH * HD * SS];    // [b,kv,hd,tok]
__device__ hf g_ctxh[(size_t)BS * DOUT];

// ---------------- helpers ----------------
__device__ __forceinline__ uint32_t smem_u32(const void* p) {
    uint32_t a;
    asm("{ .reg .u64 t; cvta.to.shared.u64 t, %1; cvt.u32.u64 %0, t; }"
        : "=r"(a) : "l"(p));
    return a;
}
__device__ __forceinline__ uint32_t pack_h(hf a, hf b) {
    uint16_t ua = *reinterpret_cast<uint16_t*>(&a);
    uint16_t ub = *reinterpret_cast<uint16_t*>(&b);
    return (uint32_t)ua | ((uint32_t)ub << 16);
}
__device__ __forceinline__ void split2h(float x, float y, hf* hi, hf* lo,
                                        size_t idx) {
    hf h0 = __float2half_rn(x), h1 = __float2half_rn(y);
    hf l0 = __float2half_rn(x - __half2float(h0));
    hf l1 = __float2half_rn(y - __half2float(h1));
    *reinterpret_cast<uint32_t*>(hi + idx) = pack_h(h0, h1);
    *reinterpret_cast<uint32_t*>(lo + idx) = pack_h(l0, l1);
}
__device__ __forceinline__ void cpasync16(uint32_t dst, const void* src) {
    asm volatile("cp.async.cg.shared.global [%0], [%1], 16;"
                 :: "r"(dst), "l"(src));
}
__device__ __forceinline__ void ldm4(uint32_t* d, uint32_t addr) {
    asm volatile("ldmatrix.sync.aligned.m8n8.x4.shared.b16 {%0,%1,%2,%3}, [%4];"
                 : "=r"(d[0]), "=r"(d[1]), "=r"(d[2]), "=r"(d[3]) : "r"(addr));
}
__device__ __forceinline__ void mma_f16(float* c, const uint32_t* a, const uint32_t* b) {
    asm volatile(
        "mma.sync.aligned.m16n8k16.row.col.f32.f16.f16.f32 "
        "{%0,%1,%2,%3}, {%4,%5,%6,%7}, {%8,%9}, {%0,%1,%2,%3};"
        : "+f"(c[0]), "+f"(c[1]), "+f"(c[2]), "+f"(c[3])
        : "r"(a[0]), "r"(a[1]), "r"(a[2]), "r"(a[3]), "r"(b[0]), "r"(b[1]));
}

// ---------------- fp16-single NT mainloop (2-stage cp.async) ------------
// acc = A[m0:+128, 0:K] @ B[n0:+128, 0:K]^T  (fp16 operands, fp32 acc)
__device__ __forceinline__ void mma_compute_f16(
    char* dyn, const hf* __restrict__ A, const hf* __restrict__ B,
    int ld, int K, int m0, int n0, float acc[4][4][4])
{
    const uint32_t sb = smem_u32(dyn);
    const int tid  = threadIdx.x;
    const int lane = tid & 31;
    const int wid  = tid >> 5;
    const int wm   = wid & 1;
    const int wn   = wid >> 1;

#pragma unroll
    for (int i = 0; i < 4; i++)
#pragma unroll
        for (int j = 0; j < 4; j++)
#pragma unroll
            for (int k = 0; k < 4; k++) acc[i][j][k] = 0.f;

    const uint32_t aoff =
        (uint32_t)(((wm * 64 + (lane & 15)) * DKP + ((lane >> 4) * 8)) * 2);
    const uint32_t boff =
        (uint32_t)(((wn * 32 + ((lane >> 4) * 8) + (lane & 7)) * DKP +
                    (((lane >> 3) & 1) * 8)) * 2);

    const int frow = tid >> 1;
    const int fseg = (tid & 1) * 16;
    const int nch = K / DBK;

    auto fill = [&](int ch) {
        const uint32_t st = sb + (uint32_t)(ch & 1) * DSTAGE;
        const int k0 = ch * DBK;
        const uint32_t so = (uint32_t)(frow * DKP + fseg) * 2;
        const size_t ai = (size_t)(m0 + frow) * ld + k0 + fseg;
        const size_t bi = (size_t)(n0 + frow) * ld + k0 + fseg;
        cpasync16(st + so, A + ai);
        cpasync16(st + so + 16, A + ai + 8);
        cpasync16(st + DTILE + so, B + bi);
        cpasync16(st + DTILE + so + 16, B + bi + 8);
        asm volatile("cp.async.commit_group;");
    };

    fill(0);
    for (int ch = 0; ch < nch; ch++) {
        if (ch + 1 < nch) {
            fill(ch + 1);
            asm volatile("cp.async.wait_group 1;");
        } else {
            asm volatile("cp.async.wait_group 0;");
        }
        __syncthreads();

        const uint32_t base = sb + (uint32_t)(ch & 1) * DSTAGE;
        const uint32_t aB = base + aoff;
        const uint32_t bB = base + DTILE + boff;
#pragma unroll
        for (int ks = 0; ks < 2; ks++) {
            uint32_t bh[8];
            ldm4(bh + 0, bB + ks * 32);
            ldm4(bh + 4, bB + 16 * DKP * 2 + ks * 32);
#pragma unroll
            for (int mt = 0; mt < 4; mt++) {
                uint32_t ah[4];
                ldm4(ah, aB + mt * 16 * DKP * 2 + ks * 32);
#pragma unroll
                for (int nt = 0; nt < 4; nt++)
                    mma_f16(acc[mt][nt], ah, &bh[nt * 2]);
            }
        }
        __syncthreads();
    }
}

// ---------------- O-projection (fp16 single) ----------------
__global__ void __launch_bounds__(NTHR)
k_mma_o(const hf* __restrict__ A, const hf* __restrict__ B,
        float* __restrict__ C)
{
    extern __shared__ char dyn[];
    const int m0 = blockIdx.y * BM, n0 = blockIdx.x * BN;
    float acc[4][4][4];
    mma_compute_f16(dyn, A, B, DOUT, DOUT, m0, n0, acc);

    const int lane = threadIdx.x & 31, wid = threadIdx.x >> 5;
    const int wm = wid & 1, wn = wid >> 1;
    const int g = lane >> 2, cq = lane & 3;
#pragma unroll
    for (int mt = 0; mt < 4; mt++)
#pragma unroll
        for (int half = 0; half < 2; half++) {
            const int row = m0 + wm * 64 + mt * 16 + g + half * 8;
#pragma unroll
            for (int nt = 0; nt < 4; nt++) {
                const int col = n0 + wn * 32 + nt * 8 + cq * 2;
                *reinterpret_cast<float2*>(C + (size_t)row * DIN + col) =
                    make_float2(acc[mt][nt][half * 2 + 0],
                                acc[mt][nt][half * 2 + 1]);
            }
        }
}

// ---------------- merged QKV fp16 GEMM + fused epilogues ----------------
__global__ void __launch_bounds__(NTHR)
k_mma_qkv(const hf* __restrict__ xh, const hf* __restrict__ W,
          hf* __restrict__ vT,
          hf* __restrict__ qhmh, hf* __restrict__ qhml,
          hf* __restrict__ khmh, hf* __restrict__ khml,
          const float* __restrict__ cosb, const float* __restrict__ sinb,
          const float* __restrict__ qs, const float* __restrict__ ks)
{
    extern __shared__ char dyn[];
    const int m0 = blockIdx.y * BM, n0 = blockIdx.x * BN;
    float acc[4][4][4];
    mma_compute_f16(dyn, xh, W, DIN, DIN, m0, n0, acc);

    const int lane = threadIdx.x & 31, wid = threadIdx.x >> 5;
    const int wm = wid & 1, wn = wid >> 1;

    if (n0 >= DOUT + DKV) {
        // ---- V tile: smem transpose -> vT[kv][hd][tok] fp16 ----
        const int kv = (n0 - DOUT - DKV) / HD;
        float* stg = reinterpret_cast<float*>(dyn);   // [128 tok][133]
#pragma unroll
        for (int mt = 0; mt < 4; mt++)
#pragma unroll
            for (int half = 0; half < 2; half++) {
                const int rl = wm * 64 + mt * 16 + (lane >> 2) + half * 8;
#pragma unroll
                for (int nt = 0; nt < 4; nt++) {
                    const int c = wn * 32 + nt * 8 + (lane & 3) * 2;
                    stg[rl * 133 + c]     = acc[mt][nt][half * 2 + 0];
                    stg[rl * 133 + c + 1] = acc[mt][nt][half * 2 + 1];
                }
            }
        __syncthreads();
        const int b = m0 >> 11, pos0 = m0 & (SS - 1);
        hf* dst = vT + (size_t)(b * KVH + kv) * HD * SS + pos0;
#pragma unroll
        for (int rr = 0; rr < 16; rr++) {
            const int r = wid * 16 + rr;              // hd row
            uint2 v;
            v.x = pack_h(__float2half_rn(stg[(lane * 4 + 0) * 133 + r]),
                         __float2half_rn(stg[(lane * 4 + 1) * 133 + r]));
            v.y = pack_h(__float2half_rn(stg[(lane * 4 + 2) * 133 + r]),
                         __float2half_rn(stg[(lane * 4 + 3) * 133 + r]));
            *reinterpret_cast<uint2*>(dst + (size_t)r * SS + lane * 4) = v;
        }
        return;
    }

    // ---- Q/K tile: rmsnorm + rope + fp16 hi/lo split, head-major ----
    const bool isQ = (n0 < DOUT);
    const float* scale = isQ ? qs : ks;
    hf* oh = isQ ? qhmh : khmh;
    hf* ol = isQ ? qhml : khml;
    const int nheads = isQ ? NH : KVH;
    const int h = (isQ ? n0 : (n0 - DOUT)) / HD;
    const float alpha = isQ ? 0.08838834764831845f : 1.0f;

    float* rsum = reinterpret_cast<float*>(dyn);                 // [128][4]
    float* stg  = reinterpret_cast<float*>(dyn + 2048);          // [128][132]

#pragma unroll
    for (int mt = 0; mt < 4; mt++)
#pragma unroll
        for (int half = 0; half < 2; half++) {
            const int rl = wm * 64 + mt * 16 + (lane >> 2) + half * 8;
            float part = 0.f;
#pragma unroll
            for (int nt = 0; nt < 4; nt++) {
                const float vx = acc[mt][nt][half * 2 + 0];
                const float vy = acc[mt][nt][half * 2 + 1];
                part += vx * vx + vy * vy;
            }
            part += __shfl_xor_sync(0xffffffffu, part, 1);
            part += __shfl_xor_sync(0xffffffffu, part, 2);
            if ((lane & 3) == 0) rsum[rl * 4 + wn] = part;
        }
    __syncthreads();

#pragma unroll
    for (int mt = 0; mt < 4; mt++)
#pragma unroll
        for (int half = 0; half < 2; half++) {
            const int rl = wm * 64 + mt * 16 + (lane >> 2) + half * 8;
            const float tot = rsum[rl * 4 + 0] + rsum[rl * 4 + 1] +
                              rsum[rl * 4 + 2] + rsum[rl * 4 + 3];
            const float rinv = rsqrtf(tot * (1.0f / HD) + 1e-6f) * alpha;
#pragma unroll
            for (int nt = 0; nt < 4; nt++) {
                const int c = wn * 32 + nt * 8 + (lane & 3) * 2;
                stg[rl * 132 + c]     = acc[mt][nt][half * 2 + 0] * rinv * scale[c];
                stg[rl * 132 + c + 1] = acc[mt][nt][half * 2 + 1] * rinv * scale[c + 1];
            }
        }
    __syncthreads();

#pragma unroll
    for (int mt = 0; mt < 4; mt++)
#pragma unroll
        for (int half = 0; half < 2; half++) {
            const int rl = wm * 64 + mt * 16 + (lane >> 2) + half * 8;
            const int row = m0 + rl;
            const int b = row >> 11, pos = row & (SS - 1);
#pragma unroll
            for (int nt = 0; nt < 4; nt++) {
                const int c = wn * 32 + nt * 8 + (lane & 3) * 2;
                const float xn0 = stg[rl * 132 + c];
                const float xn1 = stg[rl * 132 + c + 1];
                const int p = (c + 64) & 127;
                const float s0 = stg[rl * 132 + p];
                const float s1 = stg[rl * 132 + p + 1];
                const float rot0 = (c < 64) ? -s0 : s0;
                const float rot1 = (c < 64) ? -s1 : s1;
                const float o0 = xn0 * cosb[pos * HD + c]     + rot0 * sinb[pos * HD + c];
                const float o1 = xn1 * cosb[pos * HD + c + 1] + rot1 * sinb[pos * HD + c + 1];
                const size_t oi = ((size_t)(b * nheads + h) * SS + pos) * HD + c;
                split2h(o0, o1, oh, ol, oi);
            }
        }
}

// ---------------- fused flash attention (QK fp16x3, PV fp16x1) ----------
__global__ void __launch_bounds__(256, 1)
k_attn(const hf* __restrict__ qhp, const hf* __restrict__ qlp,
       const hf* __restrict__ khp, const hf* __restrict__ klp,
       const hf* __restrict__ vtp,
       hf* __restrict__ ctxh)
{
    extern __shared__ char dyn[];
    const uint32_t sb = smem_u32(dyn);
    hf* VsH = reinterpret_cast<hf*>(dyn);
    const int tid = threadIdx.x, lane = tid & 31, w = tid >> 5;
    const int bh = blockIdx.y, b = bh / NH, h = bh % NH;
    const int kvh = (bh % NH) / GRP;
    const int m0 = ((int)gridDim.x - 1 - (int)blockIdx.x) * FBM;
    const size_t qo = (size_t)bh * SS * HD;
    const size_t ko = (size_t)(b * KVH + kvh) * SS * HD;
    const size_t vo = (size_t)(b * KVH + kvh) * HD * SS;

#pragma unroll
    for (int it = 0; it < 8; it++) {
        const int c = tid + it * 256;
        const int row = c >> 4, col = (c & 15) * 8;
        const size_t gi = qo + (size_t)(m0 + row) * HD + col;
        cpasync16(sb + (uint32_t)(row * QSP + col) * 2, qhp + gi);
        cpasync16(sb + QBYTES + (uint32_t)(row * QSP + col) * 2, qlp + gi);
    }
    asm volatile("cp.async.commit_group;");
    asm volatile("cp.async.wait_group 0;");
    __syncthreads();

    uint32_t qfh[8][4], qfl[8][4];
    {
        const uint32_t ab = sb +
            (uint32_t)(((w * 16 + (lane & 15)) * QSP + (lane >> 4) * 8) * 2);
#pragma unroll
        for (int kk = 0; kk < 8; kk++) {
            ldm4(qfh[kk], ab + kk * 32);
            ldm4(qfl[kk], ab + QBYTES + kk * 32);
        }
    }
    __syncthreads();

    const int nb = m0 / FBN + 2;

    auto load_kv = [&](int i) {
        if (i < nb) {
            const int n0 = i * FBN;
            const uint32_t bufb = sb + (uint32_t)(i % 3) * FSTAGE;
#pragma unroll
            for (int it = 0; it < 4; it++) {
                const int c = tid + it * 256;
                const int krow = c >> 4, kcol = (c & 15) * 8;
                const size_t gk = ko + (size_t)(n0 + krow) * HD + kcol;
                cpasync16(bufb + (uint32_t)(krow * KSP + kcol) * 2, khp + gk);
                cpasync16(bufb + KTILE + (uint32_t)(krow * KSP + kcol) * 2, klp + gk);
                const int vrow = c >> 3, vc8 = (c & 7) * 8;
                cpasync16(bufb + 2 * KTILE + (uint32_t)(vrow * VSPH + vc8) * 2,
                          vtp + vo + (size_t)vrow * SS + n0 + vc8);
            }
        }
        asm volatile("cp.async.commit_group;");
    };

    load_kv(0);
    load_kv(1);

    float ctxa[16][4];
#pragma unroll
    for (int j = 0; j < 16; j++)
#pragma unroll
        for (int e = 0; e < 4; e++) ctxa[j][e] = 0.f;
    float mrow0 = -1e30f, mrow8 = -1e30f, lrow0 = 0.f, lrow8 = 0.f;

    const uint32_t kboff =
        (uint32_t)((((lane >> 4) * 8 + (lane & 7)) * KSP + ((lane >> 3) & 1) * 8) * 2);
    const int r0g = m0 + w * 16 + (lane >> 2);
    const int cquad = 2 * (lane & 3);
    const int g = lane >> 2;

    for (int i = 0; i < nb; i++) {
        asm volatile("cp.async.wait_group 1;");
        __syncthreads();
        load_kv(i + 2);                       // prefetch overlaps compute
        const uint32_t base = sb + (uint32_t)(i % 3) * FSTAGE;
        const int vwH = (int)((i % 3) * (FSTAGE / 2)) + (2 * KTILE) / 2;
        const int n0 = i * FBN;

        float s[8][4];
#pragma unroll
        for (int j = 0; j < 8; j++)
#pragma unroll
            for (int e = 0; e < 4; e++) s[j][e] = 0.f;

        const uint32_t kb = base + kboff;
#pragma unroll
        for (int kk = 0; kk < 8; kk++) {
#pragma unroll
            for (int ng = 0; ng < 4; ng++) {
                uint32_t bh4[4], bl4[4];
                const uint32_t a = kb + (uint32_t)(ng * 16 * KSP * 2) + kk * 32;
                ldm4(bh4, a);
                ldm4(bl4, a + KTILE);
                mma_f16(s[2 * ng + 0], qfh[kk], bh4 + 0);
                mma_f16(s[2 * ng + 0], qfl[kk], bh4 + 0);
                mma_f16(s[2 * ng + 0], qfh[kk], bl4 + 0);
                mma_f16(s[2 * ng + 1], qfh[kk], bh4 + 2);
                mma_f16(s[2 * ng + 1], qfl[kk], bh4 + 2);
                mma_f16(s[2 * ng + 1], qfh[kk], bl4 + 2);
            }
        }

        if (n0 + FBN - 1 > m0) {
#pragma unroll
            for (int j = 0; j < 8; j++) {
                const int col = n0 + j * 8 + cquad;
                if (col > r0g)         s[j][0] = -1e30f;
                if (col + 1 > r0g)     s[j][1] = -1e30f;
                if (col > r0g + 8)     s[j][2] = -1e30f;
                if (col + 1 > r0g + 8) s[j][3] = -1e30f;
            }
        }

        float mx0 = -1e30f, mx8 = -1e30f;
#pragma unroll
        for (int j = 0; j < 8; j++) {
            mx0 = fmaxf(mx0, fmaxf(s[j][0], s[j][1]));
            mx8 = fmaxf(mx8, fmaxf(s[j][2], s[j][3]));
        }
        mx0 = fmaxf(mx0, __shfl_xor_sync(0xffffffffu, mx0, 1));
        mx0 = fmaxf(mx0, __shfl_xor_sync(0xffffffffu, mx0, 2));
        mx8 = fmaxf(mx8, __shfl_xor_sync(0xffffffffu, mx8, 1));
        mx8 = fmaxf(mx8, __shfl_xor_sync(0xffffffffu, mx8, 2));

        const float mn0 = fmaxf(mrow0, mx0), mn8 = fmaxf(mrow8, mx8);
        const float sc0 = __expf(mrow0 - mn0), sc8 = __expf(mrow8 - mn8);
        mrow0 = mn0; mrow8 = mn8;

        float sum0 = 0.f, sum8 = 0.f;
        uint32_t ph[8][2];
#pragma unroll
        for (int j = 0; j < 8; j++) {
            const float e0 = __expf(s[j][0] - mn0);
            const float e1 = __expf(s[j][1] - mn0);
            const float e2 = __expf(s[j][2] - mn8);
            const float e3 = __expf(s[j][3] - mn8);
            sum0 += e0 + e1; sum8 += e2 + e3;
            ph[j][0] = pack_h(__float2half_rn(e0), __float2half_rn(e1));  // row r
            ph[j][1] = pack_h(__float2half_rn(e2), __float2half_rn(e3));  // row r+8
        }
        sum0 += __shfl_xor_sync(0xffffffffu, sum0, 1);
        sum0 += __shfl_xor_sync(0xffffffffu, sum0, 2);
        sum8 += __shfl_xor_sync(0xffffffffu, sum8, 1);
        sum8 += __shfl_xor_sync(0xffffffffu, sum8, 2);
        lrow0 = lrow0 * sc0 + sum0;
        lrow8 = lrow8 * sc8 + sum8;

#pragma unroll
        for (int j = 0; j < 16; j++) {
            ctxa[j][0] *= sc0; ctxa[j][1] *= sc0;
            ctxa[j][2] *= sc8; ctxa[j][3] *= sc8;
        }

        // PV fp16 single-term: A = exp frags, B = V[hd][tok] natural layout
#pragma unroll
        for (int t = 0; t < 4; t++) {
            const uint32_t pa[4] = { ph[2 * t][0], ph[2 * t][1],
                                     ph[2 * t + 1][0], ph[2 * t + 1][1] };
#pragma unroll
            for (int nt = 0; nt < 16; nt++) {
                const int vi = vwH + (nt * 8 + g) * VSPH + t * 16 + cquad;
                uint32_t vb[2];
                vb[0] = *reinterpret_cast<const uint32_t*>(VsH + vi);
                vb[1] = *reinterpret_cast<const uint32_t*>(VsH + vi + 8);
                mma_f16(ctxa[nt], pa, vb);
            }
        }
    }

    // epilogue: normalize + fp16 store (O-proj operand)
    const float inv0 = 1.0f / lrow0, inv8 = 1.0f / lrow8;
    const int r0 = m0 + w * 16 + (lane >> 2);
#pragma unroll
    for (int j = 0; j < 16; j++) {
        const int col = h * HD + j * 8 + cquad;
        const size_t i0 = ((size_t)b * SS + r0) * DOUT + col;
        const size_t i8 = ((size_t)b * SS + r0 + 8) * DOUT + col;
        *reinterpret_cast<uint32_t*>(ctxh + i0) =
            pack_h(__float2half_rn(ctxa[j][0] * inv0),
                   __float2half_rn(ctxa[j][1] * inv0));
        *reinterpret_cast<uint32_t*>(ctxh + i8) =
            pack_h(__float2half_rn(ctxa[j][2] * inv8),
                   __float2half_rn(ctxa[j][3] * inv8));
    }
}

// ---------------- prep kernels ----------------
__global__ void k_xhalf(const float* __restrict__ in, hf* __restrict__ outp,
                        int n)
{
    const int i = (blockIdx.x * blockDim.x + threadIdx.x) * 2;
    if (i < n) {
        float2 v = *reinterpret_cast<const float2*>(in + i);
        *reinterpret_cast<uint32_t*>(outp + i) =
            pack_h(__float2half_rn(v.x), __float2half_rn(v.y));
    }
}

// merged weight transposes -> fp16 (flat grid over Wq, Wk, Wv, Wo)
__global__ void k_wprep(const float* __restrict__ Wq, const float* __restrict__ Wk,
                        const float* __restrict__ Wv, const float* __restrict__ Wo,
                        hf* __restrict__ WTh, hf* __restrict__ WoTh)
{
    __shared__ float t[32][33];
    int bid = blockIdx.x;
    const float* src; hf* dst; int ldin, ldout, nbx;
    if (bid < 4096)      { src = Wq; dst = WTh; ldin = DOUT; ldout = DIN; nbx = 64; }
    else if (bid < 5120) { bid -= 4096; src = Wk; dst = WTh + (size_t)DOUT * DIN;
                           ldin = DKV; ldout = DIN; nbx = 16; }
    else if (bid < 6144) { bid -= 5120; src = Wv; dst = WTh + (size_t)(DOUT + DKV) * DIN;
                           ldin = DKV; ldout = DIN; nbx = 16; }
    else                 { bid -= 6144; src = Wo; dst = WoTh; ldin = DIN; ldout = DOUT; nbx = 64; }
    const int c0 = (bid % nbx) * 32, r0 = (bid / nbx) * 32;
    const int tx = threadIdx.x, ty = threadIdx.y;
#pragma unroll
    for (int i = 0; i < 32; i += 8)
        t[ty + i][tx] = src[(size_t)(r0 + ty + i) * ldin + c0 + tx];
    __syncthreads();
#pragma unroll
    for (int i = 0; i < 32; i += 8)
        dst[(size_t)(c0 + ty + i) * ldout + r0 + tx] =
            __float2half_rn(t[tx][ty + i]);
}

// ---------------- launch ----------------
extern "C" void kernel_launch(void* const* d_in, const int* in_sizes, int n_in,
                              void* d_out, int out_size)
{
    const float* x    = (const float*)d_in[0];
    const float* cosb = (const float*)d_in[2];
    const float* sinb = (const float*)d_in[3];
    const float* Wq   = (const float*)d_in[4];
    const float* Wk   = (const float*)d_in[5];
    const float* Wv   = (const float*)d_in[6];
    const float* Wo   = (const float*)d_in[7];
    const float* qs   = (const float*)d_in[8];
    const float* ks   = (const float*)d_in[9];
    float* out = (float*)d_out;

    hf *xh, *WTh, *WoTh, *qhmh, *qhml, *khmh, *khml, *vTh, *ctxh;
    cudaGetSymbolAddress((void**)&xh,   g_xh);
    cudaGetSymbolAddress((void**)&WTh,  g_WTh);
    cudaGetSymbolAddress((void**)&WoTh, g_WoTh);
    cudaGetSymbolAddress((void**)&qhmh, g_qhmh);
    cudaGetSymbolAddress((void**)&qhml, g_qhml);
    cudaGetSymbolAddress((void**)&khmh, g_khmh);
    cudaGetSymbolAddress((void**)&khml, g_khml);
    cudaGetSymbolAddress((void**)&vTh,  g_vTh);
    cudaGetSymbolAddress((void**)&ctxh, g_ctxh);

    cudaFuncSetAttribute(k_mma_qkv, cudaFuncAttributeMaxDynamicSharedMemorySize, QKV_SMEM);
    cudaFuncSetAttribute(k_mma_o,   cudaFuncAttributeMaxDynamicSharedMemorySize, DSMEM);
    cudaFuncSetAttribute(k_attn,    cudaFuncAttributeMaxDynamicSharedMemorySize, FSMEM);

    // Prep: merged fp16 weight transposes + fp16 round of x
    k_wprep<<<10240, dim3(32, 8)>>>(Wq, Wk, Wv, Wo, WTh, WoTh);
    k_xhalf<<<(BS * DIN / 2 + 255) / 256, 256>>>(x, xh, BS * DIN);

    // Merged QKV projection (fp16 single): Q/K -> normrope+split, V -> vT
    k_mma_qkv<<<dim3(NQKV / BN, BS / BM), NTHR, QKV_SMEM>>>(
        xh, WTh, vTh, qhmh, qhml, khmh, khml, cosb, sinb, qs, ks);

    // Fused flash attention (QK fp16x3, PV fp16x1; 3-stage pipeline)
    k_attn<<<dim3(SS / FBM, BB * NH), 256, FSMEM>>>(
        qhmh, qhml, khmh, khml, vTh, ctxh);

    // Output projection (fp16 single)
    k_mma_o<<<dim3(DIN / BN, BS / BM), NTHR, DSMEM>>>(ctxh, WoTh, out);
}